// round 2
// baseline (speedup 1.0000x reference)
#include <cuda_runtime.h>
#include <math.h>

#define NN  10000
#define FF  128
#define EE  640000
#define HID 64

// ---------------- device scratch (no allocations allowed) ----------------
__device__ float g_M[NN * FF];     // per-node message  M = relu(h@W1+b1)@W2+b2
__device__ float g_agg[NN * FF];   // attention-weighted aggregate
__device__ float g_ssrc[NN];       // M . (node_kernel @ a1)
__device__ float g_sdst[NN];       // h . a2
__device__ float g_v[FF];          // node_kernel @ a1
__device__ int   g_deg[NN];
__device__ int   g_off[NN + 1];
__device__ int   g_cur[NN];
__device__ int   g_esrc[EE];       // src indices sorted by dst (CSR payload)

// ---------------- small prep kernels ----------------
__global__ void k_zero_deg() {
    int i = blockIdx.x * blockDim.x + threadIdx.x;
    if (i < NN) g_deg[i] = 0;
}

__global__ void k_v(const float* __restrict__ nk, const float* __restrict__ attn) {
    int k = threadIdx.x;  // 128 threads
    float s = 0.f;
    for (int c = 0; c < FF; c++) s += nk[k * FF + c] * attn[c];
    g_v[k] = s;
}

__global__ void k_hist(const int* __restrict__ dst) {
    int e = blockIdx.x * blockDim.x + threadIdx.x;
    if (e < EE) atomicAdd(&g_deg[dst[e]], 1);
}

__global__ void k_scan() {  // 1 block, 1024 threads
    __shared__ int sd[1024];
    int t = threadIdx.x;
    const int CH = (NN + 1023) / 1024;  // 10
    int base = t * CH;
    int p = 0;
    for (int i = 0; i < CH; i++) {
        int idx = base + i;
        if (idx < NN) p += g_deg[idx];
    }
    sd[t] = p;
    __syncthreads();
    for (int o = 1; o < 1024; o <<= 1) {
        int v = (t >= o) ? sd[t - o] : 0;
        __syncthreads();
        sd[t] += v;
        __syncthreads();
    }
    int run = sd[t] - p;  // exclusive prefix
    for (int i = 0; i < CH; i++) {
        int idx = base + i;
        if (idx < NN) {
            g_off[idx] = run;
            g_cur[idx] = run;
            run += g_deg[idx];
        }
    }
    if (t == 1023) g_off[NN] = sd[1023];
}

__global__ void k_scatter(const int* __restrict__ src, const int* __restrict__ dst) {
    int e = blockIdx.x * blockDim.x + threadIdx.x;
    if (e < EE) {
        int d = dst[e];
        int p = atomicAdd(&g_cur[d], 1);
        g_esrc[p] = src[e];
    }
}

// ---------------- node MLP: M, s_src, s_dst ----------------
// Tile: 64 rows x 128 cols, 256 threads, each thread 8 rows x 4 cols.
__global__ void k_node(const float* __restrict__ h,  const float* __restrict__ W1,
                       const float* __restrict__ b1, const float* __restrict__ W2,
                       const float* __restrict__ b2, const float* __restrict__ attn) {
    extern __shared__ float sm[];
    float* hs = sm;             // 64*128
    float* t1 = sm + 64 * FF;   // 64*128
    int t = threadIdx.x;
    int row0 = blockIdx.x * 64;

    for (int i = t; i < 64 * FF; i += 256) {
        int r = i / FF, c = i % FF;
        int gr = row0 + r;
        hs[i] = (gr < NN) ? h[gr * FF + c] : 0.f;
    }
    __syncthreads();

    int tc = t & 31, tr = t >> 5;
    int c0 = 4 * tc;

    float acc[8][4];
#pragma unroll
    for (int r = 0; r < 8; r++)
#pragma unroll
        for (int j = 0; j < 4; j++) acc[r][j] = 0.f;

    // GEMM1: t1 = relu(h @ W1 + b1)
    for (int k = 0; k < FF; k++) {
        float4 b = *reinterpret_cast<const float4*>(&W1[k * FF + c0]);
#pragma unroll
        for (int r = 0; r < 8; r++) {
            float a = hs[(tr * 8 + r) * FF + k];
            acc[r][0] += a * b.x; acc[r][1] += a * b.y;
            acc[r][2] += a * b.z; acc[r][3] += a * b.w;
        }
    }
    {
        float4 bb = *reinterpret_cast<const float4*>(&b1[c0]);
#pragma unroll
        for (int r = 0; r < 8; r++) {
            float4 v;
            v.x = fmaxf(acc[r][0] + bb.x, 0.f);
            v.y = fmaxf(acc[r][1] + bb.y, 0.f);
            v.z = fmaxf(acc[r][2] + bb.z, 0.f);
            v.w = fmaxf(acc[r][3] + bb.w, 0.f);
            *reinterpret_cast<float4*>(&t1[(tr * 8 + r) * FF + c0]) = v;
        }
    }
    __syncthreads();

    // GEMM2: M = t1 @ W2 + b2
#pragma unroll
    for (int r = 0; r < 8; r++)
#pragma unroll
        for (int j = 0; j < 4; j++) acc[r][j] = 0.f;
    for (int k = 0; k < FF; k++) {
        float4 b = *reinterpret_cast<const float4*>(&W2[k * FF + c0]);
#pragma unroll
        for (int r = 0; r < 8; r++) {
            float a = t1[(tr * 8 + r) * FF + k];
            acc[r][0] += a * b.x; acc[r][1] += a * b.y;
            acc[r][2] += a * b.z; acc[r][3] += a * b.w;
        }
    }
    {
        float4 bb = *reinterpret_cast<const float4*>(&b2[c0]);
        float4 vv = *reinterpret_cast<const float4*>(&g_v[c0]);
        float4* M4 = reinterpret_cast<float4*>(g_M);
#pragma unroll
        for (int r = 0; r < 8; r++) {
            int row = row0 + tr * 8 + r;
            float4 m;
            m.x = acc[r][0] + bb.x; m.y = acc[r][1] + bb.y;
            m.z = acc[r][2] + bb.z; m.w = acc[r][3] + bb.w;
            if (row < NN) M4[row * 32 + tc] = m;
            float p = m.x * vv.x + m.y * vv.y + m.z * vv.z + m.w * vv.w;
#pragma unroll
            for (int o = 16; o > 0; o >>= 1) p += __shfl_xor_sync(0xffffffffu, p, o);
            if (tc == 0 && row < NN) g_ssrc[row] = p;
        }
    }
    // s_dst = h . a2
    {
        float4 a2 = *reinterpret_cast<const float4*>(&attn[FF + c0]);
#pragma unroll
        for (int r = 0; r < 8; r++) {
            int row = row0 + tr * 8 + r;
            float4 hv = *reinterpret_cast<const float4*>(&hs[(tr * 8 + r) * FF + c0]);
            float p = hv.x * a2.x + hv.y * a2.y + hv.z * a2.z + hv.w * a2.w;
#pragma unroll
            for (int o = 16; o > 0; o >>= 1) p += __shfl_xor_sync(0xffffffffu, p, o);
            if (tc == 0 && row < NN) g_sdst[row] = p;
        }
    }
}

// ---------------- edge aggregation: one warp per dst node ----------------
__global__ void k_edge() {
    int w = (blockIdx.x * blockDim.x + threadIdx.x) >> 5;
    int lane = threadIdx.x & 31;
    if (w >= NN) return;
    int beg = g_off[w];
    int ne = g_off[w + 1] - beg;
    float4* aggp = reinterpret_cast<float4*>(&g_agg[w * FF]) + lane;
    if (ne == 0) {
        float4 z = {0.f, 0.f, 0.f, 0.f};
        *aggp = z;
        return;
    }
    float sd = g_sdst[w];
    // pass 1: segment max of leaky_relu score
    float mx = -1e30f;
    for (int j = lane; j < ne; j += 32) {
        int s = g_esrc[beg + j];
        float e = g_ssrc[s] + sd;
        e = e > 0.f ? e : 0.2f * e;
        mx = fmaxf(mx, e);
    }
#pragma unroll
    for (int o = 16; o > 0; o >>= 1) mx = fmaxf(mx, __shfl_xor_sync(0xffffffffu, mx, o));
    // pass 2: accumulate exp-weighted messages + denominator together
    float4 acc = {0.f, 0.f, 0.f, 0.f};
    float den = 0.f;
    const float4* M4 = reinterpret_cast<const float4*>(g_M);
    for (int j = 0; j < ne; j++) {
        int s = g_esrc[beg + j];
        float e = g_ssrc[s] + sd;
        e = e > 0.f ? e : 0.2f * e;
        float ex = expf(e - mx);
        den += ex;
        float4 mv = M4[s * 32 + lane];
        acc.x += ex * mv.x; acc.y += ex * mv.y;
        acc.z += ex * mv.z; acc.w += ex * mv.w;
    }
    float inv = 1.f / (den + 1e-9f);
    acc.x *= inv; acc.y *= inv; acc.z *= inv; acc.w *= inv;
    *aggp = acc;
}

// ---------------- update + readout ----------------
// h_new = relu([agg|h] @ Wu + bu); out = relu(h_new @ Wr1 + br1) @ Wr2 + br2
__global__ void k_upd(const float* __restrict__ h,   const float* __restrict__ Wu,
                      const float* __restrict__ bu,  const float* __restrict__ Wr1,
                      const float* __restrict__ br1, const float* __restrict__ Wr2,
                      const float* __restrict__ br2, float* __restrict__ out) {
    extern __shared__ float sm[];
    float* xs = sm;              // 64*256
    float* hn = sm + 64 * 256;   // 64*128
    int t = threadIdx.x;
    int row0 = blockIdx.x * 64;

    for (int i = t; i < 64 * 256; i += 256) {
        int r = i >> 8, c = i & 255;
        int gr = row0 + r;
        float v = 0.f;
        if (gr < NN) v = (c < FF) ? g_agg[gr * FF + c] : h[gr * FF + (c - FF)];
        xs[i] = v;
    }
    __syncthreads();

    int tc = t & 31, tr = t >> 5;
    int c0 = 4 * tc;

    float acc[8][4];
#pragma unroll
    for (int r = 0; r < 8; r++)
#pragma unroll
        for (int j = 0; j < 4; j++) acc[r][j] = 0.f;
    for (int k = 0; k < 2 * FF; k++) {
        float4 b = *reinterpret_cast<const float4*>(&Wu[k * FF + c0]);
#pragma unroll
        for (int r = 0; r < 8; r++) {
            float a = xs[(tr * 8 + r) * 256 + k];
            acc[r][0] += a * b.x; acc[r][1] += a * b.y;
            acc[r][2] += a * b.z; acc[r][3] += a * b.w;
        }
    }
    {
        float4 bb = *reinterpret_cast<const float4*>(&bu[c0]);
#pragma unroll
        for (int r = 0; r < 8; r++) {
            float4 v;
            v.x = fmaxf(acc[r][0] + bb.x, 0.f);
            v.y = fmaxf(acc[r][1] + bb.y, 0.f);
            v.z = fmaxf(acc[r][2] + bb.z, 0.f);
            v.w = fmaxf(acc[r][3] + bb.w, 0.f);
            *reinterpret_cast<float4*>(&hn[(tr * 8 + r) * FF + c0]) = v;
        }
    }
    __syncthreads();

    // readout: r1 = relu(hn @ Wr1 + br1) [64 cols], out = r1 @ Wr2 + br2
    int c1 = 2 * tc;  // each thread 2 cols of 64
    float a2[8][2];
#pragma unroll
    for (int r = 0; r < 8; r++) { a2[r][0] = 0.f; a2[r][1] = 0.f; }
    for (int k = 0; k < FF; k++) {
        float2 bw = *reinterpret_cast<const float2*>(&Wr1[k * HID + c1]);
#pragma unroll
        for (int r = 0; r < 8; r++) {
            float a = hn[(tr * 8 + r) * FF + k];
            a2[r][0] += a * bw.x;
            a2[r][1] += a * bw.y;
        }
    }
    float2 w2 = *reinterpret_cast<const float2*>(&Wr2[c1]);
    float2 bb1 = *reinterpret_cast<const float2*>(&br1[c1]);
    float br2v = br2[0];
#pragma unroll
    for (int r = 0; r < 8; r++) {
        int row = row0 + tr * 8 + r;
        float x0 = fmaxf(a2[r][0] + bb1.x, 0.f);
        float x1 = fmaxf(a2[r][1] + bb1.y, 0.f);
        float p = x0 * w2.x + x1 * w2.y;
#pragma unroll
        for (int o = 16; o > 0; o >>= 1) p += __shfl_xor_sync(0xffffffffu, p, o);
        if (tc == 0 && row < NN) out[row] = p + br2v;
    }
}

// ---------------- launch ----------------
extern "C" void kernel_launch(void* const* d_in, const int* in_sizes, int n_in,
                              void* d_out, int out_size) {
    const float* h    = (const float*)d_in[0];
    const int*   src  = (const int*)d_in[1];
    const int*   dst  = (const int*)d_in[2];
    const float* W1   = (const float*)d_in[3];
    const float* b1   = (const float*)d_in[4];
    const float* W2   = (const float*)d_in[5];
    const float* b2   = (const float*)d_in[6];
    const float* nk   = (const float*)d_in[7];
    const float* attn = (const float*)d_in[8];
    const float* Wu   = (const float*)d_in[9];
    const float* bu   = (const float*)d_in[10];
    const float* Wr1  = (const float*)d_in[11];
    const float* br1  = (const float*)d_in[12];
    const float* Wr2  = (const float*)d_in[13];
    const float* br2  = (const float*)d_in[14];
    float* out = (float*)d_out;

    cudaFuncSetAttribute(k_node, cudaFuncAttributeMaxDynamicSharedMemorySize, 64 * 1024);
    cudaFuncSetAttribute(k_upd,  cudaFuncAttributeMaxDynamicSharedMemorySize, 96 * 1024);

    k_zero_deg<<<(NN + 255) / 256, 256>>>();
    k_v<<<1, 128>>>(nk, attn);
    k_hist<<<(EE + 255) / 256, 256>>>(dst);
    k_scan<<<1, 1024>>>();
    k_scatter<<<(EE + 255) / 256, 256>>>(src, dst);
    k_node<<<(NN + 63) / 64, 256, 64 * 1024>>>(h, W1, b1, W2, b2, attn);
    k_edge<<<(NN * 32 + 255) / 256, 256>>>();
    k_upd<<<(NN + 63) / 64, 256, 96 * 1024>>>(h, Wu, bu, Wr1, br1, Wr2, br2, out);
}

// round 3
// speedup vs baseline: 1.2485x; 1.2485x over previous
#include <cuda_runtime.h>
#include <math.h>

#define NN  10000
#define FF  128
#define EE  640000
#define HID 64
#define PAD 66

typedef unsigned long long ull;

// ---------------- device scratch ----------------
__device__ float g_M[NN * FF];     // per-node message
__device__ float g_agg[NN * FF];   // attention-weighted aggregate
__device__ float g_ssrc[NN];
__device__ float g_sdst[NN];
__device__ float g_v[FF];
__device__ int   g_deg[NN];
__device__ int   g_off[NN + 1];
__device__ int   g_cur[NN];
__device__ int   g_esrc[EE];

// ---------------- f32x2 helpers ----------------
__device__ __forceinline__ ull pk(float lo, float hi) {
    ull r; asm("mov.b64 %0, {%1,%2};" : "=l"(r) : "f"(lo), "f"(hi)); return r;
}
__device__ __forceinline__ float2 upk(ull v) {
    float2 r; asm("mov.b64 {%0,%1}, %2;" : "=f"(r.x), "=f"(r.y) : "l"(v)); return r;
}
__device__ __forceinline__ void fma2(ull& d, ull a, ull b) {
    asm("fma.rn.f32x2 %0, %1, %2, %0;" : "+l"(d) : "l"(a), "l"(b));
}

// ---------------- prep: zero deg + v = node_kernel @ a1 ----------------
__global__ void k_prep(const float* __restrict__ nk, const float* __restrict__ attn) {
    if (blockIdx.x < 40) {
        int i = blockIdx.x * 256 + threadIdx.x;
        if (i < NN) g_deg[i] = 0;
    } else {
        int k = threadIdx.x;
        if (k < FF) {
            float s = 0.f;
            for (int c = 0; c < FF; c++) s += nk[k * FF + c] * attn[c];
            g_v[k] = s;
        }
    }
}

__global__ void k_hist(const int4* __restrict__ dst4) {
    int i = blockIdx.x * blockDim.x + threadIdx.x;
    if (i < EE / 4) {
        int4 d = dst4[i];
        atomicAdd(&g_deg[d.x], 1); atomicAdd(&g_deg[d.y], 1);
        atomicAdd(&g_deg[d.z], 1); atomicAdd(&g_deg[d.w], 1);
    }
}

// warp-shuffle 2-level scan, 1024 threads, 1 block
__global__ void k_scan() {
    __shared__ int wsum[32], woff[32];
    int t = threadIdx.x, lane = t & 31, wid = t >> 5;
    const int CH = 10;
    int base = t * CH;
    int c[CH];
    int p = 0;
#pragma unroll
    for (int i = 0; i < CH; i++) {
        int idx = base + i;
        c[i] = (idx < NN) ? g_deg[idx] : 0;
        p += c[i];
    }
    int incl = p;
#pragma unroll
    for (int o = 1; o < 32; o <<= 1) {
        int v = __shfl_up_sync(0xffffffffu, incl, o);
        if (lane >= o) incl += v;
    }
    if (lane == 31) wsum[wid] = incl;
    __syncthreads();
    if (wid == 0) {
        int v = wsum[lane];
        int i2 = v;
#pragma unroll
        for (int o = 1; o < 32; o <<= 1) {
            int u = __shfl_up_sync(0xffffffffu, i2, o);
            if (lane >= o) i2 += u;
        }
        woff[lane] = i2 - v;
    }
    __syncthreads();
    int run = woff[wid] + incl - p;
#pragma unroll
    for (int i = 0; i < CH; i++) {
        int idx = base + i;
        if (idx < NN) {
            g_off[idx] = run;
            g_cur[idx] = run;
            run += c[i];
        }
    }
    if (t == 1023) g_off[NN] = run;
}

__global__ void k_scatter(const int4* __restrict__ src4, const int4* __restrict__ dst4) {
    int i = blockIdx.x * blockDim.x + threadIdx.x;
    if (i < EE / 4) {
        int4 s = src4[i];
        int4 d = dst4[i];
        g_esrc[atomicAdd(&g_cur[d.x], 1)] = s.x;
        g_esrc[atomicAdd(&g_cur[d.y], 1)] = s.y;
        g_esrc[atomicAdd(&g_cur[d.z], 1)] = s.z;
        g_esrc[atomicAdd(&g_cur[d.w], 1)] = s.w;
    }
}

// ---------------- node MLP: M, s_src, s_dst (f32x2, transposed smem) --------
// 64-row x 128-col tile, 256 threads, thread: 4 row-pairs x 4 cols.
__global__ void k_node(const float* __restrict__ h,  const float* __restrict__ W1,
                       const float* __restrict__ b1, const float* __restrict__ W2,
                       const float* __restrict__ b2, const float* __restrict__ attn) {
    extern __shared__ float sm[];
    float* hsT = sm;                // [128 k][64 r] pad 66
    float* t1T = sm + FF * PAD;     // [128 c][64 r] pad 66
    int t = threadIdx.x;
    int row0 = blockIdx.x * 64;

    for (int i = t; i < 64 * FF; i += 256) {
        int r = i >> 7, c = i & 127;
        int gr = row0 + r;
        hsT[c * PAD + r] = (gr < NN) ? h[gr * FF + c] : 0.f;
    }
    __syncthreads();

    int tc = t & 31, tr = t >> 5;
    int c0 = 4 * tc;
    int rb = tr * 8;

    ull acc[4][4];
#pragma unroll
    for (int p = 0; p < 4; p++)
#pragma unroll
        for (int c = 0; c < 4; c++) acc[p][c] = 0ull;

    // GEMM1: t1 = relu(h@W1 + b1)
    for (int k = 0; k < FF; k++) {
        float4 b = *reinterpret_cast<const float4*>(&W1[k * FF + c0]);
        ull bb0 = pk(b.x, b.x), bb1 = pk(b.y, b.y), bb2 = pk(b.z, b.z), bb3 = pk(b.w, b.w);
        const ull* ap = reinterpret_cast<const ull*>(&hsT[k * PAD + rb]);
        ull a0 = ap[0], a1 = ap[1], a2 = ap[2], a3 = ap[3];
        fma2(acc[0][0], a0, bb0); fma2(acc[0][1], a0, bb1); fma2(acc[0][2], a0, bb2); fma2(acc[0][3], a0, bb3);
        fma2(acc[1][0], a1, bb0); fma2(acc[1][1], a1, bb1); fma2(acc[1][2], a1, bb2); fma2(acc[1][3], a1, bb3);
        fma2(acc[2][0], a2, bb0); fma2(acc[2][1], a2, bb1); fma2(acc[2][2], a2, bb2); fma2(acc[2][3], a2, bb3);
        fma2(acc[3][0], a3, bb0); fma2(acc[3][1], a3, bb1); fma2(acc[3][2], a3, bb2); fma2(acc[3][3], a3, bb3);
    }
    {
        float4 bb = *reinterpret_cast<const float4*>(&b1[c0]);
        float bv[4] = {bb.x, bb.y, bb.z, bb.w};
#pragma unroll
        for (int p = 0; p < 4; p++)
#pragma unroll
            for (int c = 0; c < 4; c++) {
                float2 v = upk(acc[p][c]);
                v.x = fmaxf(v.x + bv[c], 0.f);
                v.y = fmaxf(v.y + bv[c], 0.f);
                *reinterpret_cast<ull*>(&t1T[(c0 + c) * PAD + rb + 2 * p]) = pk(v.x, v.y);
            }
    }
    __syncthreads();

    // GEMM2: M = t1 @ W2 + b2
#pragma unroll
    for (int p = 0; p < 4; p++)
#pragma unroll
        for (int c = 0; c < 4; c++) acc[p][c] = 0ull;
    for (int k = 0; k < FF; k++) {
        float4 b = *reinterpret_cast<const float4*>(&W2[k * FF + c0]);
        ull bb0 = pk(b.x, b.x), bb1 = pk(b.y, b.y), bb2 = pk(b.z, b.z), bb3 = pk(b.w, b.w);
        const ull* ap = reinterpret_cast<const ull*>(&t1T[k * PAD + rb]);
        ull a0 = ap[0], a1 = ap[1], a2 = ap[2], a3 = ap[3];
        fma2(acc[0][0], a0, bb0); fma2(acc[0][1], a0, bb1); fma2(acc[0][2], a0, bb2); fma2(acc[0][3], a0, bb3);
        fma2(acc[1][0], a1, bb0); fma2(acc[1][1], a1, bb1); fma2(acc[1][2], a1, bb2); fma2(acc[1][3], a1, bb3);
        fma2(acc[2][0], a2, bb0); fma2(acc[2][1], a2, bb1); fma2(acc[2][2], a2, bb2); fma2(acc[2][3], a2, bb3);
        fma2(acc[3][0], a3, bb0); fma2(acc[3][1], a3, bb1); fma2(acc[3][2], a3, bb2); fma2(acc[3][3], a3, bb3);
    }
    {
        float4 bb = *reinterpret_cast<const float4*>(&b2[c0]);
        float4 vv = *reinterpret_cast<const float4*>(&g_v[c0]);
        float4* M4 = reinterpret_cast<float4*>(g_M);
#pragma unroll
        for (int p = 0; p < 4; p++) {
            int rlo = row0 + rb + 2 * p;
            int rhi = rlo + 1;
            float2 m0 = upk(acc[p][0]), m1 = upk(acc[p][1]), m2 = upk(acc[p][2]), m3 = upk(acc[p][3]);
            float4 lo = {m0.x + bb.x, m1.x + bb.y, m2.x + bb.z, m3.x + bb.w};
            float4 hi = {m0.y + bb.x, m1.y + bb.y, m2.y + bb.z, m3.y + bb.w};
            if (rlo < NN) M4[rlo * 32 + tc] = lo;
            if (rhi < NN) M4[rhi * 32 + tc] = hi;
            float plo = lo.x * vv.x + lo.y * vv.y + lo.z * vv.z + lo.w * vv.w;
            float phi = hi.x * vv.x + hi.y * vv.y + hi.z * vv.z + hi.w * vv.w;
#pragma unroll
            for (int o = 16; o > 0; o >>= 1) {
                plo += __shfl_xor_sync(0xffffffffu, plo, o);
                phi += __shfl_xor_sync(0xffffffffu, phi, o);
            }
            if (tc == 0) {
                if (rlo < NN) g_ssrc[rlo] = plo;
                if (rhi < NN) g_ssrc[rhi] = phi;
            }
        }
    }
    // s_dst = h . a2 (read hsT back)
    {
        float4 a2 = *reinterpret_cast<const float4*>(&attn[FF + c0]);
#pragma unroll
        for (int r = 0; r < 8; r++) {
            int row = row0 + rb + r;
            float h0 = hsT[(c0 + 0) * PAD + rb + r];
            float h1 = hsT[(c0 + 1) * PAD + rb + r];
            float h2 = hsT[(c0 + 2) * PAD + rb + r];
            float h3 = hsT[(c0 + 3) * PAD + rb + r];
            float p = h0 * a2.x + h1 * a2.y + h2 * a2.z + h3 * a2.w;
#pragma unroll
            for (int o = 16; o > 0; o >>= 1) p += __shfl_xor_sync(0xffffffffu, p, o);
            if (tc == 0 && row < NN) g_sdst[row] = p;
        }
    }
}

// ---------------- edge aggregation: one warp per dst ----------------
__global__ void k_edge() {
    __shared__ float sbuf[8][128];
    int w = (blockIdx.x * blockDim.x + threadIdx.x) >> 5;
    int wl = threadIdx.x >> 5;
    int lane = threadIdx.x & 31;
    if (w >= NN) return;
    int beg = g_off[w];
    int ne = g_off[w + 1] - beg;
    float4* aggp = reinterpret_cast<float4*>(&g_agg[w * FF]) + lane;
    if (ne == 0) {
        float4 z = {0.f, 0.f, 0.f, 0.f};
        *aggp = z;
        return;
    }
    float sd = g_sdst[w];
    bool cached = (ne <= 128);
    float mx = -1e30f;
    for (int j = lane; j < ne; j += 32) {
        int s = g_esrc[beg + j];
        float e = g_ssrc[s] + sd;
        e = e > 0.f ? e : 0.2f * e;
        if (cached) sbuf[wl][j] = e;
        mx = fmaxf(mx, e);
    }
#pragma unroll
    for (int o = 16; o > 0; o >>= 1) mx = fmaxf(mx, __shfl_xor_sync(0xffffffffu, mx, o));
    __syncwarp();

    float4 acc = {0.f, 0.f, 0.f, 0.f};
    float den = 0.f;
    const float4* M4 = reinterpret_cast<const float4*>(g_M);
    if (cached) {
        int j = 0;
        for (; j + 4 <= ne; j += 4) {
            int s0 = g_esrc[beg + j],     s1 = g_esrc[beg + j + 1];
            int s2 = g_esrc[beg + j + 2], s3 = g_esrc[beg + j + 3];
            float ex0 = __expf(sbuf[wl][j]     - mx);
            float ex1 = __expf(sbuf[wl][j + 1] - mx);
            float ex2 = __expf(sbuf[wl][j + 2] - mx);
            float ex3 = __expf(sbuf[wl][j + 3] - mx);
            float4 m0 = M4[s0 * 32 + lane], m1 = M4[s1 * 32 + lane];
            float4 m2 = M4[s2 * 32 + lane], m3 = M4[s3 * 32 + lane];
            den += (ex0 + ex1) + (ex2 + ex3);
            acc.x += ex0 * m0.x + ex1 * m1.x + ex2 * m2.x + ex3 * m3.x;
            acc.y += ex0 * m0.y + ex1 * m1.y + ex2 * m2.y + ex3 * m3.y;
            acc.z += ex0 * m0.z + ex1 * m1.z + ex2 * m2.z + ex3 * m3.z;
            acc.w += ex0 * m0.w + ex1 * m1.w + ex2 * m2.w + ex3 * m3.w;
        }
        for (; j < ne; j++) {
            int s = g_esrc[beg + j];
            float ex = __expf(sbuf[wl][j] - mx);
            float4 mv = M4[s * 32 + lane];
            den += ex;
            acc.x += ex * mv.x; acc.y += ex * mv.y;
            acc.z += ex * mv.z; acc.w += ex * mv.w;
        }
    } else {
        for (int j = 0; j < ne; j++) {
            int s = g_esrc[beg + j];
            float e = g_ssrc[s] + sd;
            e = e > 0.f ? e : 0.2f * e;
            float ex = __expf(e - mx);
            float4 mv = M4[s * 32 + lane];
            den += ex;
            acc.x += ex * mv.x; acc.y += ex * mv.y;
            acc.z += ex * mv.z; acc.w += ex * mv.w;
        }
    }
    float inv = 1.f / (den + 1e-9f);
    acc.x *= inv; acc.y *= inv; acc.z *= inv; acc.w *= inv;
    *aggp = acc;
}

// ---------------- update + readout (f32x2, transposed smem) ----------------
__global__ void k_upd(const float* __restrict__ h,   const float* __restrict__ Wu,
                      const float* __restrict__ bu,  const float* __restrict__ Wr1,
                      const float* __restrict__ br1, const float* __restrict__ Wr2,
                      const float* __restrict__ br2, float* __restrict__ out) {
    extern __shared__ float sm[];
    float* xsT = sm;                    // [256 k][64 r] pad 66
    float* hnT = sm + 256 * PAD;        // [128 c][64 r] pad 66
    int t = threadIdx.x;
    int row0 = blockIdx.x * 64;

    for (int i = t; i < 64 * 256; i += 256) {
        int r = i >> 8, c = i & 255;
        int gr = row0 + r;
        float v = 0.f;
        if (gr < NN) v = (c < FF) ? g_agg[gr * FF + c] : h[gr * FF + (c - FF)];
        xsT[c * PAD + r] = v;
    }
    __syncthreads();

    int tc = t & 31, tr = t >> 5;
    int c0 = 4 * tc;
    int rb = tr * 8;

    ull acc[4][4];
#pragma unroll
    for (int p = 0; p < 4; p++)
#pragma unroll
        for (int c = 0; c < 4; c++) acc[p][c] = 0ull;

    for (int k = 0; k < 2 * FF; k++) {
        float4 b = *reinterpret_cast<const float4*>(&Wu[k * FF + c0]);
        ull bb0 = pk(b.x, b.x), bb1 = pk(b.y, b.y), bb2 = pk(b.z, b.z), bb3 = pk(b.w, b.w);
        const ull* ap = reinterpret_cast<const ull*>(&xsT[k * PAD + rb]);
        ull a0 = ap[0], a1 = ap[1], a2 = ap[2], a3 = ap[3];
        fma2(acc[0][0], a0, bb0); fma2(acc[0][1], a0, bb1); fma2(acc[0][2], a0, bb2); fma2(acc[0][3], a0, bb3);
        fma2(acc[1][0], a1, bb0); fma2(acc[1][1], a1, bb1); fma2(acc[1][2], a1, bb2); fma2(acc[1][3], a1, bb3);
        fma2(acc[2][0], a2, bb0); fma2(acc[2][1], a2, bb1); fma2(acc[2][2], a2, bb2); fma2(acc[2][3], a2, bb3);
        fma2(acc[3][0], a3, bb0); fma2(acc[3][1], a3, bb1); fma2(acc[3][2], a3, bb2); fma2(acc[3][3], a3, bb3);
    }
    {
        float4 bb = *reinterpret_cast<const float4*>(&bu[c0]);
        float bv[4] = {bb.x, bb.y, bb.z, bb.w};
#pragma unroll
        for (int p = 0; p < 4; p++)
#pragma unroll
            for (int c = 0; c < 4; c++) {
                float2 v = upk(acc[p][c]);
                v.x = fmaxf(v.x + bv[c], 0.f);
                v.y = fmaxf(v.y + bv[c], 0.f);
                *reinterpret_cast<ull*>(&hnT[(c0 + c) * PAD + rb + 2 * p]) = pk(v.x, v.y);
            }
    }
    __syncthreads();

    // readout: r1 = relu(hn @ Wr1 + br1); out = r1 @ Wr2 + br2
    int c1 = 2 * tc;
    ull ar[4][2];
#pragma unroll
    for (int p = 0; p < 4; p++) { ar[p][0] = 0ull; ar[p][1] = 0ull; }
    for (int k = 0; k < FF; k++) {
        float2 bw = *reinterpret_cast<const float2*>(&Wr1[k * HID + c1]);
        ull bbx = pk(bw.x, bw.x), bby = pk(bw.y, bw.y);
        const ull* ap = reinterpret_cast<const ull*>(&hnT[k * PAD + rb]);
        ull a0 = ap[0], a1 = ap[1], a2 = ap[2], a3 = ap[3];
        fma2(ar[0][0], a0, bbx); fma2(ar[0][1], a0, bby);
        fma2(ar[1][0], a1, bbx); fma2(ar[1][1], a1, bby);
        fma2(ar[2][0], a2, bbx); fma2(ar[2][1], a2, bby);
        fma2(ar[3][0], a3, bbx); fma2(ar[3][1], a3, bby);
    }
    {
        float2 w2  = *reinterpret_cast<const float2*>(&Wr2[c1]);
        float2 bb1 = *reinterpret_cast<const float2*>(&br1[c1]);
        float br2v = br2[0];
#pragma unroll
        for (int p = 0; p < 4; p++) {
            int rlo = row0 + rb + 2 * p;
            int rhi = rlo + 1;
            float2 q0 = upk(ar[p][0]);
            float2 q1 = upk(ar[p][1]);
            float plo = fmaxf(q0.x + bb1.x, 0.f) * w2.x + fmaxf(q1.x + bb1.y, 0.f) * w2.y;
            float phi = fmaxf(q0.y + bb1.x, 0.f) * w2.x + fmaxf(q1.y + bb1.y, 0.f) * w2.y;
#pragma unroll
            for (int o = 16; o > 0; o >>= 1) {
                plo += __shfl_xor_sync(0xffffffffu, plo, o);
                phi += __shfl_xor_sync(0xffffffffu, phi, o);
            }
            if (tc == 0) {
                if (rlo < NN) out[rlo] = plo + br2v;
                if (rhi < NN) out[rhi] = phi + br2v;
            }
        }
    }
}

// ---------------- launch ----------------
extern "C" void kernel_launch(void* const* d_in, const int* in_sizes, int n_in,
                              void* d_out, int out_size) {
    const float* h    = (const float*)d_in[0];
    const int*   src  = (const int*)d_in[1];
    const int*   dst  = (const int*)d_in[2];
    const float* W1   = (const float*)d_in[3];
    const float* b1   = (const float*)d_in[4];
    const float* W2   = (const float*)d_in[5];
    const float* b2   = (const float*)d_in[6];
    const float* nk   = (const float*)d_in[7];
    const float* attn = (const float*)d_in[8];
    const float* Wu   = (const float*)d_in[9];
    const float* bu   = (const float*)d_in[10];
    const float* Wr1  = (const float*)d_in[11];
    const float* br1  = (const float*)d_in[12];
    const float* Wr2  = (const float*)d_in[13];
    const float* br2  = (const float*)d_in[14];
    float* out = (float*)d_out;

    const int smem_node = 2 * FF * PAD * sizeof(float);             // 67584
    const int smem_upd  = (256 + 128) * PAD * sizeof(float);        // 101376
    cudaFuncSetAttribute(k_node, cudaFuncAttributeMaxDynamicSharedMemorySize, smem_node);
    cudaFuncSetAttribute(k_upd,  cudaFuncAttributeMaxDynamicSharedMemorySize, smem_upd);

    k_prep<<<41, 256>>>(nk, attn);
    k_hist<<<(EE / 4 + 255) / 256, 256>>>((const int4*)dst);
    k_scan<<<1, 1024>>>();
    k_scatter<<<(EE / 4 + 255) / 256, 256>>>((const int4*)src, (const int4*)dst);
    k_node<<<(NN + 63) / 64, 256, smem_node>>>(h, W1, b1, W2, b2, attn);
    k_edge<<<(NN * 32 + 255) / 256, 256>>>();
    k_upd<<<(NN + 63) / 64, 256, smem_upd>>>(h, Wu, bu, Wr1, br1, Wr2, br2, out);
}

// round 5
// speedup vs baseline: 1.3957x; 1.1179x over previous
#include <cuda_runtime.h>
#include <cuda_fp16.h>
#include <math.h>

#define NN  10000
#define FF  128
#define EE  640000
#define HID 64
#define PAD 66

typedef unsigned long long ull;

// ---------------- device scratch ----------------
__device__ __half g_Mh[NN * FF];   // per-node message, fp16 (edge path only)
__device__ float  g_agg[NN * FF];  // attention-weighted aggregate (fp32)
__device__ float  g_ssrc[NN];
__device__ float  g_sdst[NN];
__device__ float  g_v[FF];
__device__ int    g_deg[NN];
__device__ int    g_off[NN + 1];
__device__ int    g_rank[EE];
__device__ int2   g_edge[EE];      // {src, score_bits} sorted by dst

// ---------------- f32x2 helpers ----------------
__device__ __forceinline__ ull pk(float lo, float hi) {
    ull r; asm("mov.b64 %0, {%1,%2};" : "=l"(r) : "f"(lo), "f"(hi)); return r;
}
__device__ __forceinline__ float2 upk(ull v) {
    float2 r; asm("mov.b64 {%0,%1}, %2;" : "=f"(r.x), "=f"(r.y) : "l"(v)); return r;
}
__device__ __forceinline__ void fma2(ull& d, ull a, ull b) {
    asm("fma.rn.f32x2 %0, %1, %2, %0;" : "+l"(d) : "l"(a), "l"(b));
}

// ---------------- prep: zero deg + v = node_kernel @ a1 ----------------
__global__ void k_prep(const float* __restrict__ nk, const float* __restrict__ attn) {
    if (blockIdx.x < 40) {
        int i = blockIdx.x * 256 + threadIdx.x;
        if (i < NN) g_deg[i] = 0;
    } else {
        int k = threadIdx.x;
        if (k < FF) {
            float s = 0.f;
            for (int c = 0; c < FF; c++) s += nk[k * FF + c] * attn[c];
            g_v[k] = s;
        }
    }
}

// histogram + per-edge rank (returned atomic)
__global__ void k_hist(const int4* __restrict__ dst4) {
    int i = blockIdx.x * blockDim.x + threadIdx.x;
    if (i < EE / 4) {
        int4 d = dst4[i];
        int4 r;
        r.x = atomicAdd(&g_deg[d.x], 1);
        r.y = atomicAdd(&g_deg[d.y], 1);
        r.z = atomicAdd(&g_deg[d.z], 1);
        r.w = atomicAdd(&g_deg[d.w], 1);
        reinterpret_cast<int4*>(g_rank)[i] = r;
    }
}

// warp-shuffle 2-level scan, 1024 threads, 1 block
__global__ void k_scan() {
    __shared__ int wsum[32], woff[32];
    int t = threadIdx.x, lane = t & 31, wid = t >> 5;
    const int CH = 10;
    int base = t * CH;
    int c[CH];
    int p = 0;
#pragma unroll
    for (int i = 0; i < CH; i++) {
        int idx = base + i;
        c[i] = (idx < NN) ? g_deg[idx] : 0;
        p += c[i];
    }
    int incl = p;
#pragma unroll
    for (int o = 1; o < 32; o <<= 1) {
        int v = __shfl_up_sync(0xffffffffu, incl, o);
        if (lane >= o) incl += v;
    }
    if (lane == 31) wsum[wid] = incl;
    __syncthreads();
    if (wid == 0) {
        int v = wsum[lane];
        int i2 = v;
#pragma unroll
        for (int o = 1; o < 32; o <<= 1) {
            int u = __shfl_up_sync(0xffffffffu, i2, o);
            if (lane >= o) i2 += u;
        }
        woff[lane] = i2 - v;
    }
    __syncthreads();
    int run = woff[wid] + incl - p;
#pragma unroll
    for (int i = 0; i < CH; i++) {
        int idx = base + i;
        if (idx < NN) {
            g_off[idx] = run;
            run += c[i];
        }
    }
    if (t == 1023) g_off[NN] = run;
}

// atomic-free scatter + fused score computation (runs AFTER k_node)
__global__ void k_scatter(const int4* __restrict__ src4, const int4* __restrict__ dst4) {
    int i = blockIdx.x * blockDim.x + threadIdx.x;
    if (i < EE / 4) {
        int4 s = src4[i];
        int4 d = dst4[i];
        int4 r = reinterpret_cast<const int4*>(g_rank)[i];
#pragma unroll
        for (int q = 0; q < 4; q++) {
            int ss = (q == 0) ? s.x : (q == 1) ? s.y : (q == 2) ? s.z : s.w;
            int dd = (q == 0) ? d.x : (q == 1) ? d.y : (q == 2) ? d.z : d.w;
            int rr = (q == 0) ? r.x : (q == 1) ? r.y : (q == 2) ? r.z : r.w;
            float e = g_ssrc[ss] + g_sdst[dd];
            e = e > 0.f ? e : 0.2f * e;
            g_edge[g_off[dd] + rr] = make_int2(ss, __float_as_int(e));
        }
    }
}

// ---------------- node MLP: Mh (fp16), s_src, s_dst ----------------
// 64-row x 128-col tile, 256 threads, thread: 4 row-pairs x 4 cols (f32x2).
__global__ void k_node(const float* __restrict__ h,  const float* __restrict__ W1,
                       const float* __restrict__ b1, const float* __restrict__ W2,
                       const float* __restrict__ b2, const float* __restrict__ attn) {
    extern __shared__ float sm[];
    float* hsT = sm;                // [128 k][64 r] pad 66
    float* t1T = sm + FF * PAD;     // [128 c][64 r] pad 66
    int t = threadIdx.x;
    int row0 = blockIdx.x * 64;

    for (int i = t; i < 64 * FF; i += 256) {
        int r = i >> 7, c = i & 127;
        int gr = row0 + r;
        hsT[c * PAD + r] = (gr < NN) ? h[gr * FF + c] : 0.f;
    }
    __syncthreads();

    int tc = t & 31, tr = t >> 5;
    int c0 = 4 * tc;
    int rb = tr * 8;

    ull acc[4][4];
#pragma unroll
    for (int p = 0; p < 4; p++)
#pragma unroll
        for (int c = 0; c < 4; c++) acc[p][c] = 0ull;

    // GEMM1: t1 = relu(h@W1 + b1)
    for (int k = 0; k < FF; k++) {
        float4 b = *reinterpret_cast<const float4*>(&W1[k * FF + c0]);
        ull bb0 = pk(b.x, b.x), bb1 = pk(b.y, b.y), bb2 = pk(b.z, b.z), bb3 = pk(b.w, b.w);
        const ull* ap = reinterpret_cast<const ull*>(&hsT[k * PAD + rb]);
        ull a0 = ap[0], a1 = ap[1], a2 = ap[2], a3 = ap[3];
        fma2(acc[0][0], a0, bb0); fma2(acc[0][1], a0, bb1); fma2(acc[0][2], a0, bb2); fma2(acc[0][3], a0, bb3);
        fma2(acc[1][0], a1, bb0); fma2(acc[1][1], a1, bb1); fma2(acc[1][2], a1, bb2); fma2(acc[1][3], a1, bb3);
        fma2(acc[2][0], a2, bb0); fma2(acc[2][1], a2, bb1); fma2(acc[2][2], a2, bb2); fma2(acc[2][3], a2, bb3);
        fma2(acc[3][0], a3, bb0); fma2(acc[3][1], a3, bb1); fma2(acc[3][2], a3, bb2); fma2(acc[3][3], a3, bb3);
    }
    {
        float4 bb = *reinterpret_cast<const float4*>(&b1[c0]);
        float bv[4] = {bb.x, bb.y, bb.z, bb.w};
#pragma unroll
        for (int p = 0; p < 4; p++)
#pragma unroll
            for (int c = 0; c < 4; c++) {
                float2 v = upk(acc[p][c]);
                v.x = fmaxf(v.x + bv[c], 0.f);
                v.y = fmaxf(v.y + bv[c], 0.f);
                *reinterpret_cast<ull*>(&t1T[(c0 + c) * PAD + rb + 2 * p]) = pk(v.x, v.y);
            }
    }
    __syncthreads();

    // GEMM2: M = t1 @ W2 + b2  -> store fp16
#pragma unroll
    for (int p = 0; p < 4; p++)
#pragma unroll
        for (int c = 0; c < 4; c++) acc[p][c] = 0ull;
    for (int k = 0; k < FF; k++) {
        float4 b = *reinterpret_cast<const float4*>(&W2[k * FF + c0]);
        ull bb0 = pk(b.x, b.x), bb1 = pk(b.y, b.y), bb2 = pk(b.z, b.z), bb3 = pk(b.w, b.w);
        const ull* ap = reinterpret_cast<const ull*>(&t1T[k * PAD + rb]);
        ull a0 = ap[0], a1 = ap[1], a2 = ap[2], a3 = ap[3];
        fma2(acc[0][0], a0, bb0); fma2(acc[0][1], a0, bb1); fma2(acc[0][2], a0, bb2); fma2(acc[0][3], a0, bb3);
        fma2(acc[1][0], a1, bb0); fma2(acc[1][1], a1, bb1); fma2(acc[1][2], a1, bb2); fma2(acc[1][3], a1, bb3);
        fma2(acc[2][0], a2, bb0); fma2(acc[2][1], a2, bb1); fma2(acc[2][2], a2, bb2); fma2(acc[2][3], a2, bb3);
        fma2(acc[3][0], a3, bb0); fma2(acc[3][1], a3, bb1); fma2(acc[3][2], a3, bb2); fma2(acc[3][3], a3, bb3);
    }
    {
        float4 bb = *reinterpret_cast<const float4*>(&b2[c0]);
        float4 vv = *reinterpret_cast<const float4*>(&g_v[c0]);
        uint2* Mh2 = reinterpret_cast<uint2*>(g_Mh);
#pragma unroll
        for (int p = 0; p < 4; p++) {
            int rlo = row0 + rb + 2 * p;
            int rhi = rlo + 1;
            float2 m0 = upk(acc[p][0]), m1 = upk(acc[p][1]), m2 = upk(acc[p][2]), m3 = upk(acc[p][3]);
            float4 lo = {m0.x + bb.x, m1.x + bb.y, m2.x + bb.z, m3.x + bb.w};
            float4 hi = {m0.y + bb.x, m1.y + bb.y, m2.y + bb.z, m3.y + bb.w};
            if (rlo < NN) {
                __half2 h0 = __floats2half2_rn(lo.x, lo.y);
                __half2 h1 = __floats2half2_rn(lo.z, lo.w);
                Mh2[rlo * 32 + tc] = make_uint2(*reinterpret_cast<unsigned*>(&h0),
                                                *reinterpret_cast<unsigned*>(&h1));
            }
            if (rhi < NN) {
                __half2 h0 = __floats2half2_rn(hi.x, hi.y);
                __half2 h1 = __floats2half2_rn(hi.z, hi.w);
                Mh2[rhi * 32 + tc] = make_uint2(*reinterpret_cast<unsigned*>(&h0),
                                                *reinterpret_cast<unsigned*>(&h1));
            }
            float plo = lo.x * vv.x + lo.y * vv.y + lo.z * vv.z + lo.w * vv.w;
            float phi = hi.x * vv.x + hi.y * vv.y + hi.z * vv.z + hi.w * vv.w;
#pragma unroll
            for (int o = 16; o > 0; o >>= 1) {
                plo += __shfl_xor_sync(0xffffffffu, plo, o);
                phi += __shfl_xor_sync(0xffffffffu, phi, o);
            }
            if (tc == 0) {
                if (rlo < NN) g_ssrc[rlo] = plo;
                if (rhi < NN) g_ssrc[rhi] = phi;
            }
        }
    }
    // s_dst = h . a2
    {
        float4 a2 = *reinterpret_cast<const float4*>(&attn[FF + c0]);
#pragma unroll
        for (int r = 0; r < 8; r++) {
            int row = row0 + rb + r;
            float h0 = hsT[(c0 + 0) * PAD + rb + r];
            float h1 = hsT[(c0 + 1) * PAD + rb + r];
            float h2 = hsT[(c0 + 2) * PAD + rb + r];
            float h3 = hsT[(c0 + 3) * PAD + rb + r];
            float p = h0 * a2.x + h1 * a2.y + h2 * a2.z + h3 * a2.w;
#pragma unroll
            for (int o = 16; o > 0; o >>= 1) p += __shfl_xor_sync(0xffffffffu, p, o);
            if (tc == 0 && row < NN) g_sdst[row] = p;
        }
    }
}

// ---------------- edge aggregation: one warp per dst ----------------
__global__ void k_edge() {
    int w = (blockIdx.x * blockDim.x + threadIdx.x) >> 5;
    int lane = threadIdx.x & 31;
    if (w >= NN) return;
    int beg = g_off[w];
    int ne = g_off[w + 1] - beg;
    float4* aggp = reinterpret_cast<float4*>(&g_agg[w * FF]) + lane;
    if (ne == 0) {
        float4 z = {0.f, 0.f, 0.f, 0.f};
        *aggp = z;
        return;
    }
    // pass 1: segment max of precomputed scores (coalesced)
    float mx = -1e30f;
    for (int j = lane; j < ne; j += 32) {
        int2 p = g_edge[beg + j];
        mx = fmaxf(mx, __int_as_float(p.y));
    }
#pragma unroll
    for (int o = 16; o > 0; o >>= 1) mx = fmaxf(mx, __shfl_xor_sync(0xffffffffu, mx, o));

    // pass 2: accumulate exp-weighted fp16 messages + denominator
    float4 acc = {0.f, 0.f, 0.f, 0.f};
    float den = 0.f;
    const uint2* Mh2 = reinterpret_cast<const uint2*>(g_Mh);
    int j = 0;
    for (; j + 4 <= ne; j += 4) {
        int2 e0 = g_edge[beg + j],     e1 = g_edge[beg + j + 1];
        int2 e2 = g_edge[beg + j + 2], e3 = g_edge[beg + j + 3];
        float ex0 = __expf(__int_as_float(e0.y) - mx);
        float ex1 = __expf(__int_as_float(e1.y) - mx);
        float ex2 = __expf(__int_as_float(e2.y) - mx);
        float ex3 = __expf(__int_as_float(e3.y) - mx);
        uint2 u0 = Mh2[e0.x * 32 + lane], u1 = Mh2[e1.x * 32 + lane];
        uint2 u2 = Mh2[e2.x * 32 + lane], u3 = Mh2[e3.x * 32 + lane];
        den += (ex0 + ex1) + (ex2 + ex3);
        float2 a0 = __half22float2(*reinterpret_cast<__half2*>(&u0.x));
        float2 b0 = __half22float2(*reinterpret_cast<__half2*>(&u0.y));
        float2 a1 = __half22float2(*reinterpret_cast<__half2*>(&u1.x));
        float2 b1 = __half22float2(*reinterpret_cast<__half2*>(&u1.y));
        float2 a2 = __half22float2(*reinterpret_cast<__half2*>(&u2.x));
        float2 b2 = __half22float2(*reinterpret_cast<__half2*>(&u2.y));
        float2 a3 = __half22float2(*reinterpret_cast<__half2*>(&u3.x));
        float2 b3 = __half22float2(*reinterpret_cast<__half2*>(&u3.y));
        acc.x += ex0 * a0.x + ex1 * a1.x + ex2 * a2.x + ex3 * a3.x;
        acc.y += ex0 * a0.y + ex1 * a1.y + ex2 * a2.y + ex3 * a3.y;
        acc.z += ex0 * b0.x + ex1 * b1.x + ex2 * b2.x + ex3 * b3.x;
        acc.w += ex0 * b0.y + ex1 * b1.y + ex2 * b2.y + ex3 * b3.y;
    }
    for (; j < ne; j++) {
        int2 e0 = g_edge[beg + j];
        float ex = __expf(__int_as_float(e0.y) - mx);
        uint2 u0 = Mh2[e0.x * 32 + lane];
        float2 a0 = __half22float2(*reinterpret_cast<__half2*>(&u0.x));
        float2 b0 = __half22float2(*reinterpret_cast<__half2*>(&u0.y));
        den += ex;
        acc.x += ex * a0.x; acc.y += ex * a0.y;
        acc.z += ex * b0.x; acc.w += ex * b0.y;
    }
    float inv = 1.f / (den + 1e-9f);
    acc.x *= inv; acc.y *= inv; acc.z *= inv; acc.w *= inv;
    *aggp = acc;
}

// ---------------- update + readout (f32x2, transposed smem) ----------------
__global__ void k_upd(const float* __restrict__ h,   const float* __restrict__ Wu,
                      const float* __restrict__ bu,  const float* __restrict__ Wr1,
                      const float* __restrict__ br1, const float* __restrict__ Wr2,
                      const float* __restrict__ br2, float* __restrict__ out) {
    extern __shared__ float sm[];
    float* xsT = sm;                    // [256 k][64 r] pad 66
    float* hnT = sm + 256 * PAD;        // [128 c][64 r] pad 66
    int t = threadIdx.x;
    int row0 = blockIdx.x * 64;

    for (int i = t; i < 64 * 256; i += 256) {
        int r = i >> 8, c = i & 255;
        int gr = row0 + r;
        float v = 0.f;
        if (gr < NN) v = (c < FF) ? g_agg[gr * FF + c] : h[gr * FF + (c - FF)];
        xsT[c * PAD + r] = v;
    }
    __syncthreads();

    int tc = t & 31, tr = t >> 5;
    int c0 = 4 * tc;
    int rb = tr * 8;

    ull acc[4][4];
#pragma unroll
    for (int p = 0; p < 4; p++)
#pragma unroll
        for (int c = 0; c < 4; c++) acc[p][c] = 0ull;

    for (int k = 0; k < 2 * FF; k++) {
        float4 b = *reinterpret_cast<const float4*>(&Wu[k * FF + c0]);
        ull bb0 = pk(b.x, b.x), bb1 = pk(b.y, b.y), bb2 = pk(b.z, b.z), bb3 = pk(b.w, b.w);
        const ull* ap = reinterpret_cast<const ull*>(&xsT[k * PAD + rb]);
        ull a0 = ap[0], a1 = ap[1], a2 = ap[2], a3 = ap[3];
        fma2(acc[0][0], a0, bb0); fma2(acc[0][1], a0, bb1); fma2(acc[0][2], a0, bb2); fma2(acc[0][3], a0, bb3);
        fma2(acc[1][0], a1, bb0); fma2(acc[1][1], a1, bb1); fma2(acc[1][2], a1, bb2); fma2(acc[1][3], a1, bb3);
        fma2(acc[2][0], a2, bb0); fma2(acc[2][1], a2, bb1); fma2(acc[2][2], a2, bb2); fma2(acc[2][3], a2, bb3);
        fma2(acc[3][0], a3, bb0); fma2(acc[3][1], a3, bb1); fma2(acc[3][2], a3, bb2); fma2(acc[3][3], a3, bb3);
    }
    {
        float4 bb = *reinterpret_cast<const float4*>(&bu[c0]);
        float bv[4] = {bb.x, bb.y, bb.z, bb.w};
#pragma unroll
        for (int p = 0; p < 4; p++)
#pragma unroll
            for (int c = 0; c < 4; c++) {
                float2 v = upk(acc[p][c]);
                v.x = fmaxf(v.x + bv[c], 0.f);
                v.y = fmaxf(v.y + bv[c], 0.f);
                *reinterpret_cast<ull*>(&hnT[(c0 + c) * PAD + rb + 2 * p]) = pk(v.x, v.y);
            }
    }
    __syncthreads();

    // readout: r1 = relu(hn @ Wr1 + br1); out = r1 @ Wr2 + br2
    int c1 = 2 * tc;
    ull ar[4][2];
#pragma unroll
    for (int p = 0; p < 4; p++) { ar[p][0] = 0ull; ar[p][1] = 0ull; }
    for (int k = 0; k < FF; k++) {
        float2 bw = *reinterpret_cast<const float2*>(&Wr1[k * HID + c1]);
        ull bbx = pk(bw.x, bw.x), bby = pk(bw.y, bw.y);
        const ull* ap = reinterpret_cast<const ull*>(&hnT[k * PAD + rb]);
        ull a0 = ap[0], a1 = ap[1], a2 = ap[2], a3 = ap[3];
        fma2(ar[0][0], a0, bbx); fma2(ar[0][1], a0, bby);
        fma2(ar[1][0], a1, bbx); fma2(ar[1][1], a1, bby);
        fma2(ar[2][0], a2, bbx); fma2(ar[2][1], a2, bby);
        fma2(ar[3][0], a3, bbx); fma2(ar[3][1], a3, bby);
    }
    {
        float2 w2  = *reinterpret_cast<const float2*>(&Wr2[c1]);
        float2 bb1 = *reinterpret_cast<const float2*>(&br1[c1]);
        float br2v = br2[0];
#pragma unroll
        for (int p = 0; p < 4; p++) {
            int rlo = row0 + rb + 2 * p;
            int rhi = rlo + 1;
            float2 q0 = upk(ar[p][0]);
            float2 q1 = upk(ar[p][1]);
            float plo = fmaxf(q0.x + bb1.x, 0.f) * w2.x + fmaxf(q1.x + bb1.y, 0.f) * w2.y;
            float phi = fmaxf(q0.y + bb1.x, 0.f) * w2.x + fmaxf(q1.y + bb1.y, 0.f) * w2.y;
#pragma unroll
            for (int o = 16; o > 0; o >>= 1) {
                plo += __shfl_xor_sync(0xffffffffu, plo, o);
                phi += __shfl_xor_sync(0xffffffffu, phi, o);
            }
            if (tc == 0) {
                if (rlo < NN) out[rlo] = plo + br2v;
                if (rhi < NN) out[rhi] = phi + br2v;
            }
        }
    }
}

// ---------------- launch ----------------
extern "C" void kernel_launch(void* const* d_in, const int* in_sizes, int n_in,
                              void* d_out, int out_size) {
    const float* h    = (const float*)d_in[0];
    const int*   src  = (const int*)d_in[1];
    const int*   dst  = (const int*)d_in[2];
    const float* W1   = (const float*)d_in[3];
    const float* b1   = (const float*)d_in[4];
    const float* W2   = (const float*)d_in[5];
    const float* b2   = (const float*)d_in[6];
    const float* nk   = (const float*)d_in[7];
    const float* attn = (const float*)d_in[8];
    const float* Wu   = (const float*)d_in[9];
    const float* bu   = (const float*)d_in[10];
    const float* Wr1  = (const float*)d_in[11];
    const float* br1  = (const float*)d_in[12];
    const float* Wr2  = (const float*)d_in[13];
    const float* br2  = (const float*)d_in[14];
    float* out = (float*)d_out;

    const int smem_node = 2 * FF * PAD * sizeof(float);             // 67584
    const int smem_upd  = (256 + 128) * PAD * sizeof(float);        // 101376
    cudaFuncSetAttribute(k_node, cudaFuncAttributeMaxDynamicSharedMemorySize, smem_node);
    cudaFuncSetAttribute(k_upd,  cudaFuncAttributeMaxDynamicSharedMemorySize, smem_upd);

    k_prep<<<41, 256>>>(nk, attn);
    k_hist<<<(EE / 4 + 255) / 256, 256>>>((const int4*)dst);
    k_scan<<<1, 1024>>>();
    k_node<<<(NN + 63) / 64, 256, smem_node>>>(h, W1, b1, W2, b2, attn);
    k_scatter<<<(EE / 4 + 255) / 256, 256>>>((const int4*)src, (const int4*)dst);
    k_edge<<<(NN * 32 + 255) / 256, 256>>>();
    k_upd<<<(NN + 63) / 64, 256, smem_upd>>>(h, Wu, bu, Wr1, br1, Wr2, br2, out);
}

// round 6
// speedup vs baseline: 1.4294x; 1.0241x over previous
#include <cuda_runtime.h>
#include <cuda_fp16.h>
#include <math.h>

#define NN  10000
#define FF  128
#define EE  640000
#define HID 64
#define PADR 18   // 16 rows + 2 pad (even, for LDS.64 alignment)

typedef unsigned long long ull;

// ---------------- device scratch ----------------
__device__ __half g_Mh[NN * FF];   // per-node message, fp16 (edge path only)
__device__ float  g_agg[NN * FF];  // attention-weighted aggregate (fp32)
__device__ float  g_ssrc[NN];
__device__ float  g_sdst[NN];
__device__ float  g_v[FF];
__device__ int    g_deg[NN];
__device__ int    g_off[NN + 1];
__device__ int    g_rank[EE];
__device__ int2   g_edge[EE];      // {src, score_bits} sorted by dst

// ---------------- f32x2 helpers ----------------
__device__ __forceinline__ ull pk(float lo, float hi) {
    ull r; asm("mov.b64 %0, {%1,%2};" : "=l"(r) : "f"(lo), "f"(hi)); return r;
}
__device__ __forceinline__ float2 upk(ull v) {
    float2 r; asm("mov.b64 {%0,%1}, %2;" : "=f"(r.x), "=f"(r.y) : "l"(v)); return r;
}
__device__ __forceinline__ void fma2(ull& d, ull a, ull b) {
    asm("fma.rn.f32x2 %0, %1, %2, %0;" : "+l"(d) : "l"(a), "l"(b));
}

// ---------------- prep: zero deg + v = node_kernel @ a1 ----------------
__global__ void k_prep(const float* __restrict__ nk, const float* __restrict__ attn) {
    if (blockIdx.x < 40) {
        int i = blockIdx.x * 256 + threadIdx.x;
        if (i < NN) g_deg[i] = 0;
    } else {
        int k = threadIdx.x;
        if (k < FF) {
            float s = 0.f;
            for (int c = 0; c < FF; c++) s += nk[k * FF + c] * attn[c];
            g_v[k] = s;
        }
    }
}

// histogram + per-edge rank (returned atomic)
__global__ void k_hist(const int4* __restrict__ dst4) {
    int i = blockIdx.x * blockDim.x + threadIdx.x;
    if (i < EE / 4) {
        int4 d = dst4[i];
        int4 r;
        r.x = atomicAdd(&g_deg[d.x], 1);
        r.y = atomicAdd(&g_deg[d.y], 1);
        r.z = atomicAdd(&g_deg[d.z], 1);
        r.w = atomicAdd(&g_deg[d.w], 1);
        reinterpret_cast<int4*>(g_rank)[i] = r;
    }
}

// warp-shuffle 2-level scan, 1024 threads, 1 block
__global__ void k_scan() {
    __shared__ int wsum[32], woff[32];
    int t = threadIdx.x, lane = t & 31, wid = t >> 5;
    const int CH = 10;
    int base = t * CH;
    int c[CH];
    int p = 0;
#pragma unroll
    for (int i = 0; i < CH; i++) {
        int idx = base + i;
        c[i] = (idx < NN) ? g_deg[idx] : 0;
        p += c[i];
    }
    int incl = p;
#pragma unroll
    for (int o = 1; o < 32; o <<= 1) {
        int v = __shfl_up_sync(0xffffffffu, incl, o);
        if (lane >= o) incl += v;
    }
    if (lane == 31) wsum[wid] = incl;
    __syncthreads();
    if (wid == 0) {
        int v = wsum[lane];
        int i2 = v;
#pragma unroll
        for (int o = 1; o < 32; o <<= 1) {
            int u = __shfl_up_sync(0xffffffffu, i2, o);
            if (lane >= o) i2 += u;
        }
        woff[lane] = i2 - v;
    }
    __syncthreads();
    int run = woff[wid] + incl - p;
#pragma unroll
    for (int i = 0; i < CH; i++) {
        int idx = base + i;
        if (idx < NN) {
            g_off[idx] = run;
            run += c[i];
        }
    }
    if (t == 1023) g_off[NN] = run;
}

// atomic-free scatter + fused score computation (runs AFTER k_node)
__global__ void k_scatter(const int4* __restrict__ src4, const int4* __restrict__ dst4) {
    int i = blockIdx.x * blockDim.x + threadIdx.x;
    if (i < EE / 4) {
        int4 s = src4[i];
        int4 d = dst4[i];
        int4 r = reinterpret_cast<const int4*>(g_rank)[i];
#pragma unroll
        for (int q = 0; q < 4; q++) {
            int ss = (q == 0) ? s.x : (q == 1) ? s.y : (q == 2) ? s.z : s.w;
            int dd = (q == 0) ? d.x : (q == 1) ? d.y : (q == 2) ? d.z : d.w;
            int rr = (q == 0) ? r.x : (q == 1) ? r.y : (q == 2) ? r.z : r.w;
            float e = g_ssrc[ss] + g_sdst[dd];
            e = e > 0.f ? e : 0.2f * e;
            g_edge[g_off[dd] + rr] = make_int2(ss, __float_as_int(e));
        }
    }
}

// ---------------- node MLP: Mh (fp16), s_src, s_dst ----------------
// 16-row x 128-col tile, 256 threads: thread = 1 row-pair x 4 cols (f32x2).
// grid = 625 -> ~4 blocks/SM for latency hiding.
__global__ void __launch_bounds__(256)
k_node(const float* __restrict__ h,  const float* __restrict__ W1,
       const float* __restrict__ b1, const float* __restrict__ W2,
       const float* __restrict__ b2, const float* __restrict__ attn) {
    __shared__ float hsT[FF * PADR];   // [128 k][16 r]
    __shared__ float t1T[FF * PADR];   // [128 c][16 r]
    int t = threadIdx.x;
    int row0 = blockIdx.x * 16;

    for (int i = t; i < 16 * FF; i += 256) {
        int r = i >> 7, c = i & 127;
        int gr = row0 + r;
        hsT[c * PADR + r] = (gr < NN) ? h[gr * FF + c] : 0.f;
    }
    __syncthreads();

    int tc = t & 31, tr = t >> 5;       // tr: warp id = row-pair id (0..7)
    int c0 = 4 * tc;
    int rb = 2 * tr;

    ull acc[4];
#pragma unroll
    for (int c = 0; c < 4; c++) acc[c] = 0ull;

    // GEMM1: t1 = relu(h@W1 + b1)
    for (int k = 0; k < FF; k++) {
        float4 b = *reinterpret_cast<const float4*>(&W1[k * FF + c0]);
        ull a = *reinterpret_cast<const ull*>(&hsT[k * PADR + rb]);
        fma2(acc[0], a, pk(b.x, b.x));
        fma2(acc[1], a, pk(b.y, b.y));
        fma2(acc[2], a, pk(b.z, b.z));
        fma2(acc[3], a, pk(b.w, b.w));
    }
    {
        float4 bb = *reinterpret_cast<const float4*>(&b1[c0]);
        float bv[4] = {bb.x, bb.y, bb.z, bb.w};
#pragma unroll
        for (int c = 0; c < 4; c++) {
            float2 v = upk(acc[c]);
            v.x = fmaxf(v.x + bv[c], 0.f);
            v.y = fmaxf(v.y + bv[c], 0.f);
            *reinterpret_cast<ull*>(&t1T[(c0 + c) * PADR + rb]) = pk(v.x, v.y);
        }
    }
    __syncthreads();

    // GEMM2: M = t1 @ W2 + b2 -> fp16
#pragma unroll
    for (int c = 0; c < 4; c++) acc[c] = 0ull;
    for (int k = 0; k < FF; k++) {
        float4 b = *reinterpret_cast<const float4*>(&W2[k * FF + c0]);
        ull a = *reinterpret_cast<const ull*>(&t1T[k * PADR + rb]);
        fma2(acc[0], a, pk(b.x, b.x));
        fma2(acc[1], a, pk(b.y, b.y));
        fma2(acc[2], a, pk(b.z, b.z));
        fma2(acc[3], a, pk(b.w, b.w));
    }
    {
        float4 bb = *reinterpret_cast<const float4*>(&b2[c0]);
        float4 vv = *reinterpret_cast<const float4*>(&g_v[c0]);
        uint2* Mh2 = reinterpret_cast<uint2*>(g_Mh);
        int rlo = row0 + rb;
        int rhi = rlo + 1;
        float2 m0 = upk(acc[0]), m1 = upk(acc[1]), m2 = upk(acc[2]), m3 = upk(acc[3]);
        float4 lo = {m0.x + bb.x, m1.x + bb.y, m2.x + bb.z, m3.x + bb.w};
        float4 hi = {m0.y + bb.x, m1.y + bb.y, m2.y + bb.z, m3.y + bb.w};
        if (rlo < NN) {
            __half2 h0 = __floats2half2_rn(lo.x, lo.y);
            __half2 h1 = __floats2half2_rn(lo.z, lo.w);
            Mh2[rlo * 32 + tc] = make_uint2(*reinterpret_cast<unsigned*>(&h0),
                                            *reinterpret_cast<unsigned*>(&h1));
        }
        if (rhi < NN) {
            __half2 h0 = __floats2half2_rn(hi.x, hi.y);
            __half2 h1 = __floats2half2_rn(hi.z, hi.w);
            Mh2[rhi * 32 + tc] = make_uint2(*reinterpret_cast<unsigned*>(&h0),
                                            *reinterpret_cast<unsigned*>(&h1));
        }
        float plo = lo.x * vv.x + lo.y * vv.y + lo.z * vv.z + lo.w * vv.w;
        float phi = hi.x * vv.x + hi.y * vv.y + hi.z * vv.z + hi.w * vv.w;
#pragma unroll
        for (int o = 16; o > 0; o >>= 1) {
            plo += __shfl_xor_sync(0xffffffffu, plo, o);
            phi += __shfl_xor_sync(0xffffffffu, phi, o);
        }
        if (tc == 0) {
            if (rlo < NN) g_ssrc[rlo] = plo;
            if (rhi < NN) g_ssrc[rhi] = phi;
        }
    }
    // s_dst = h . a2
    {
        float4 a2 = *reinterpret_cast<const float4*>(&attn[FF + c0]);
#pragma unroll
        for (int r = 0; r < 2; r++) {
            int row = row0 + rb + r;
            float h0 = hsT[(c0 + 0) * PADR + rb + r];
            float h1 = hsT[(c0 + 1) * PADR + rb + r];
            float h2 = hsT[(c0 + 2) * PADR + rb + r];
            float h3 = hsT[(c0 + 3) * PADR + rb + r];
            float p = h0 * a2.x + h1 * a2.y + h2 * a2.z + h3 * a2.w;
#pragma unroll
            for (int o = 16; o > 0; o >>= 1) p += __shfl_xor_sync(0xffffffffu, p, o);
            if (tc == 0 && row < NN) g_sdst[row] = p;
        }
    }
}

// ---------------- edge aggregation: one warp per dst ----------------
__global__ void k_edge() {
    int w = (blockIdx.x * blockDim.x + threadIdx.x) >> 5;
    int lane = threadIdx.x & 31;
    if (w >= NN) return;
    int beg = g_off[w];
    int ne = g_off[w + 1] - beg;
    float4* aggp = reinterpret_cast<float4*>(&g_agg[w * FF]) + lane;
    if (ne == 0) {
        float4 z = {0.f, 0.f, 0.f, 0.f};
        *aggp = z;
        return;
    }
    float mx = -1e30f;
    for (int j = lane; j < ne; j += 32) {
        int2 p = g_edge[beg + j];
        mx = fmaxf(mx, __int_as_float(p.y));
    }
#pragma unroll
    for (int o = 16; o > 0; o >>= 1) mx = fmaxf(mx, __shfl_xor_sync(0xffffffffu, mx, o));

    float4 acc = {0.f, 0.f, 0.f, 0.f};
    float den = 0.f;
    const uint2* Mh2 = reinterpret_cast<const uint2*>(g_Mh);
    int j = 0;
    for (; j + 4 <= ne; j += 4) {
        int2 e0 = g_edge[beg + j],     e1 = g_edge[beg + j + 1];
        int2 e2 = g_edge[beg + j + 2], e3 = g_edge[beg + j + 3];
        float ex0 = __expf(__int_as_float(e0.y) - mx);
        float ex1 = __expf(__int_as_float(e1.y) - mx);
        float ex2 = __expf(__int_as_float(e2.y) - mx);
        float ex3 = __expf(__int_as_float(e3.y) - mx);
        uint2 u0 = Mh2[e0.x * 32 + lane], u1 = Mh2[e1.x * 32 + lane];
        uint2 u2 = Mh2[e2.x * 32 + lane], u3 = Mh2[e3.x * 32 + lane];
        den += (ex0 + ex1) + (ex2 + ex3);
        float2 a0 = __half22float2(*reinterpret_cast<__half2*>(&u0.x));
        float2 b0 = __half22float2(*reinterpret_cast<__half2*>(&u0.y));
        float2 a1 = __half22float2(*reinterpret_cast<__half2*>(&u1.x));
        float2 b1 = __half22float2(*reinterpret_cast<__half2*>(&u1.y));
        float2 a2 = __half22float2(*reinterpret_cast<__half2*>(&u2.x));
        float2 b2 = __half22float2(*reinterpret_cast<__half2*>(&u2.y));
        float2 a3 = __half22float2(*reinterpret_cast<__half2*>(&u3.x));
        float2 b3 = __half22float2(*reinterpret_cast<__half2*>(&u3.y));
        acc.x += ex0 * a0.x + ex1 * a1.x + ex2 * a2.x + ex3 * a3.x;
        acc.y += ex0 * a0.y + ex1 * a1.y + ex2 * a2.y + ex3 * a3.y;
        acc.z += ex0 * b0.x + ex1 * b1.x + ex2 * b2.x + ex3 * b3.x;
        acc.w += ex0 * b0.y + ex1 * b1.y + ex2 * b2.y + ex3 * b3.y;
    }
    for (; j < ne; j++) {
        int2 e0 = g_edge[beg + j];
        float ex = __expf(__int_as_float(e0.y) - mx);
        uint2 u0 = Mh2[e0.x * 32 + lane];
        float2 a0 = __half22float2(*reinterpret_cast<__half2*>(&u0.x));
        float2 b0 = __half22float2(*reinterpret_cast<__half2*>(&u0.y));
        den += ex;
        acc.x += ex * a0.x; acc.y += ex * a0.y;
        acc.z += ex * b0.x; acc.w += ex * b0.y;
    }
    float inv = 1.f / (den + 1e-9f);
    acc.x *= inv; acc.y *= inv; acc.z *= inv; acc.w *= inv;
    *aggp = acc;
}

// ---------------- update + readout (16-row tiles) ----------------
__global__ void __launch_bounds__(256)
k_upd(const float* __restrict__ h,   const float* __restrict__ Wu,
      const float* __restrict__ bu,  const float* __restrict__ Wr1,
      const float* __restrict__ br1, const float* __restrict__ Wr2,
      const float* __restrict__ br2, float* __restrict__ out) {
    __shared__ float xsT[2 * FF * PADR];   // [256 k][16 r]
    __shared__ float hnT[FF * PADR];       // [128 c][16 r]
    int t = threadIdx.x;
    int row0 = blockIdx.x * 16;

    for (int i = t; i < 16 * 256; i += 256) {
        int r = i >> 8, c = i & 255;
        int gr = row0 + r;
        float v = 0.f;
        if (gr < NN) v = (c < FF) ? g_agg[gr * FF + c] : h[gr * FF + (c - FF)];
        xsT[c * PADR + r] = v;
    }
    __syncthreads();

    int tc = t & 31, tr = t >> 5;
    int c0 = 4 * tc;
    int rb = 2 * tr;

    ull acc[4];
#pragma unroll
    for (int c = 0; c < 4; c++) acc[c] = 0ull;

    for (int k = 0; k < 2 * FF; k++) {
        float4 b = *reinterpret_cast<const float4*>(&Wu[k * FF + c0]);
        ull a = *reinterpret_cast<const ull*>(&xsT[k * PADR + rb]);
        fma2(acc[0], a, pk(b.x, b.x));
        fma2(acc[1], a, pk(b.y, b.y));
        fma2(acc[2], a, pk(b.z, b.z));
        fma2(acc[3], a, pk(b.w, b.w));
    }
    {
        float4 bb = *reinterpret_cast<const float4*>(&bu[c0]);
        float bv[4] = {bb.x, bb.y, bb.z, bb.w};
#pragma unroll
        for (int c = 0; c < 4; c++) {
            float2 v = upk(acc[c]);
            v.x = fmaxf(v.x + bv[c], 0.f);
            v.y = fmaxf(v.y + bv[c], 0.f);
            *reinterpret_cast<ull*>(&hnT[(c0 + c) * PADR + rb]) = pk(v.x, v.y);
        }
    }
    __syncthreads();

    // readout: r1 = relu(hn @ Wr1 + br1); out = r1 @ Wr2 + br2
    int c1 = 2 * tc;
    ull ar[2] = {0ull, 0ull};
    for (int k = 0; k < FF; k++) {
        float2 bw = *reinterpret_cast<const float2*>(&Wr1[k * HID + c1]);
        ull a = *reinterpret_cast<const ull*>(&hnT[k * PADR + rb]);
        fma2(ar[0], a, pk(bw.x, bw.x));
        fma2(ar[1], a, pk(bw.y, bw.y));
    }
    {
        float2 w2  = *reinterpret_cast<const float2*>(&Wr2[c1]);
        float2 bb1 = *reinterpret_cast<const float2*>(&br1[c1]);
        float br2v = br2[0];
        int rlo = row0 + rb;
        int rhi = rlo + 1;
        float2 q0 = upk(ar[0]);
        float2 q1 = upk(ar[1]);
        float plo = fmaxf(q0.x + bb1.x, 0.f) * w2.x + fmaxf(q1.x + bb1.y, 0.f) * w2.y;
        float phi = fmaxf(q0.y + bb1.x, 0.f) * w2.x + fmaxf(q1.y + bb1.y, 0.f) * w2.y;
#pragma unroll
        for (int o = 16; o > 0; o >>= 1) {
            plo += __shfl_xor_sync(0xffffffffu, plo, o);
            phi += __shfl_xor_sync(0xffffffffu, phi, o);
        }
        if (tc == 0) {
            if (rlo < NN) out[rlo] = plo + br2v;
            if (rhi < NN) out[rhi] = phi + br2v;
        }
    }
}

// ---------------- launch ----------------
extern "C" void kernel_launch(void* const* d_in, const int* in_sizes, int n_in,
                              void* d_out, int out_size) {
    const float* h    = (const float*)d_in[0];
    const int*   src  = (const int*)d_in[1];
    const int*   dst  = (const int*)d_in[2];
    const float* W1   = (const float*)d_in[3];
    const float* b1   = (const float*)d_in[4];
    const float* W2   = (const float*)d_in[5];
    const float* b2   = (const float*)d_in[6];
    const float* nk   = (const float*)d_in[7];
    const float* attn = (const float*)d_in[8];
    const float* Wu   = (const float*)d_in[9];
    const float* bu   = (const float*)d_in[10];
    const float* Wr1  = (const float*)d_in[11];
    const float* br1  = (const float*)d_in[12];
    const float* Wr2  = (const float*)d_in[13];
    const float* br2  = (const float*)d_in[14];
    float* out = (float*)d_out;

    k_prep<<<41, 256>>>(nk, attn);
    k_hist<<<(EE / 4 + 255) / 256, 256>>>((const int4*)dst);
    k_scan<<<1, 1024>>>();
    k_node<<<(NN + 15) / 16, 256>>>(h, W1, b1, W2, b2, attn);
    k_scatter<<<(EE / 4 + 255) / 256, 256>>>((const int4*)src, (const int4*)dst);
    k_edge<<<(NN * 32 + 255) / 256, 256>>>();
    k_upd<<<(NN + 15) / 16, 256>>>(h, Wu, bu, Wr1, br1, Wr2, br2, out);
}

// round 8
// speedup vs baseline: 1.5004x; 1.0497x over previous
#include <cuda_runtime.h>
#include <cuda_fp16.h>
#include <math.h>

#define NN  10000
#define FF  128
#define EE  640000
#define HID 64
#define TRW 32    // rows per GEMM tile
#define PKS 36    // padded row stride (floats) for transposed activations

typedef unsigned long long ull;

// ---------------- device scratch ----------------
__device__ __half g_Mh[NN * FF];   // per-node message, fp16 (edge path only)
__device__ float  g_agg[NN * FF];  // attention-weighted aggregate (fp32)
__device__ float  g_ssrc[NN];
__device__ float  g_sdst[NN];
__device__ float  g_v[FF];
__device__ int    g_deg[NN];
__device__ int    g_off[NN + 1];
__device__ int    g_rank[EE];
__device__ int2   g_edge[EE];      // {src, score_bits} sorted by dst

// ---------------- helpers ----------------
__device__ __forceinline__ ull pk(float lo, float hi) {
    ull r; asm("mov.b64 %0, {%1,%2};" : "=l"(r) : "f"(lo), "f"(hi)); return r;
}
__device__ __forceinline__ float2 upk(ull v) {
    float2 r; asm("mov.b64 {%0,%1}, %2;" : "=f"(r.x), "=f"(r.y) : "l"(v)); return r;
}
__device__ __forceinline__ void fma2(ull& d, ull a, ull b) {
    asm("fma.rn.f32x2 %0, %1, %2, %0;" : "+l"(d) : "l"(a), "l"(b));
}
// 16B shared load returning two packed f32x2 operands (row pairs)
__device__ __forceinline__ void lds2x2(ull& a01, ull& a23, const float* p) {
    unsigned addr = (unsigned)__cvta_generic_to_shared(p);
    asm("ld.shared.v2.u64 {%0,%1}, [%2];" : "=l"(a01), "=l"(a23) : "r"(addr));
}

// ---------------- prep: zero deg + v = node_kernel @ a1 ----------------
__global__ void k_prep(const float* __restrict__ nk, const float* __restrict__ attn) {
    if (blockIdx.x < 40) {
        int i = blockIdx.x * 256 + threadIdx.x;
        if (i < NN) g_deg[i] = 0;
    } else {
        int k = threadIdx.x;
        if (k < FF) {
            float s = 0.f;
            for (int c = 0; c < FF; c++) s += nk[k * FF + c] * attn[c];
            g_v[k] = s;
        }
    }
}

// histogram + per-edge rank (returned atomic)
__global__ void k_hist(const int4* __restrict__ dst4) {
    int i = blockIdx.x * blockDim.x + threadIdx.x;
    if (i < EE / 4) {
        int4 d = dst4[i];
        int4 r;
        r.x = atomicAdd(&g_deg[d.x], 1);
        r.y = atomicAdd(&g_deg[d.y], 1);
        r.z = atomicAdd(&g_deg[d.z], 1);
        r.w = atomicAdd(&g_deg[d.w], 1);
        reinterpret_cast<int4*>(g_rank)[i] = r;
    }
}

// warp-shuffle 2-level scan, 1024 threads, 1 block
__global__ void k_scan() {
    __shared__ int wsum[32], woff[32];
    int t = threadIdx.x, lane = t & 31, wid = t >> 5;
    const int CH = 10;
    int base = t * CH;
    int c[CH];
    int p = 0;
#pragma unroll
    for (int i = 0; i < CH; i++) {
        int idx = base + i;
        c[i] = (idx < NN) ? g_deg[idx] : 0;
        p += c[i];
    }
    int incl = p;
#pragma unroll
    for (int o = 1; o < 32; o <<= 1) {
        int v = __shfl_up_sync(0xffffffffu, incl, o);
        if (lane >= o) incl += v;
    }
    if (lane == 31) wsum[wid] = incl;
    __syncthreads();
    if (wid == 0) {
        int v = wsum[lane];
        int i2 = v;
#pragma unroll
        for (int o = 1; o < 32; o <<= 1) {
            int u = __shfl_up_sync(0xffffffffu, i2, o);
            if (lane >= o) i2 += u;
        }
        woff[lane] = i2 - v;
    }
    __syncthreads();
    int run = woff[wid] + incl - p;
#pragma unroll
    for (int i = 0; i < CH; i++) {
        int idx = base + i;
        if (idx < NN) {
            g_off[idx] = run;
            run += c[i];
        }
    }
    if (t == 1023) g_off[NN] = run;
}

// atomic-free scatter + fused score computation (runs AFTER k_node)
__global__ void k_scatter(const int4* __restrict__ src4, const int4* __restrict__ dst4) {
    int i = blockIdx.x * blockDim.x + threadIdx.x;
    if (i < EE / 4) {
        int4 s = src4[i];
        int4 d = dst4[i];
        int4 r = reinterpret_cast<const int4*>(g_rank)[i];
#pragma unroll
        for (int q = 0; q < 4; q++) {
            int ss = (q == 0) ? s.x : (q == 1) ? s.y : (q == 2) ? s.z : s.w;
            int dd = (q == 0) ? d.x : (q == 1) ? d.y : (q == 2) ? d.z : d.w;
            int rr = (q == 0) ? r.x : (q == 1) ? r.y : (q == 2) ? r.z : r.w;
            float e = g_ssrc[ss] + g_sdst[dd];
            e = e > 0.f ? e : 0.2f * e;
            g_edge[g_off[dd] + rr] = make_int2(ss, __float_as_int(e));
        }
    }
}

// ---------------- node MLP with smem-staged weights ----------------
// 32-row x 128-col tile, 256 threads: thread = 2 row-pairs x 4 cols.
// W chunks (32k x 128c = 16KB) double-buffered in smem.
__global__ void __launch_bounds__(256)
k_node(const float* __restrict__ h,  const float* __restrict__ W1,
       const float* __restrict__ b1, const float* __restrict__ W2,
       const float* __restrict__ b2, const float* __restrict__ attn) {
    extern __shared__ float sm[];
    float* actT = sm;             // [128 k][36 r]  (holds h, then t1)
    float* wb   = sm + FF * PKS;  // [2][32*128]
    int t = threadIdx.x;
    int tc = t & 31, tw = t >> 5;
    int c0 = 4 * tc, rb = 4 * tw;
    int row0 = blockIdx.x * TRW;

    // load h tile transposed (coalesced global reads)
    for (int i = t; i < TRW * FF; i += 256) {
        int c = i & 127, r = i >> 7;
        int gr = row0 + r;
        actT[c * PKS + r] = (gr < NN) ? h[gr * FF + c] : 0.f;
    }
    __syncthreads();

    // s_dst = h . a2 (while actT holds h)
    {
        float4 a2 = *reinterpret_cast<const float4*>(&attn[FF + c0]);
#pragma unroll
        for (int rr = 0; rr < 4; rr++) {
            int row = row0 + rb + rr;
            float p = actT[(c0 + 0) * PKS + rb + rr] * a2.x
                    + actT[(c0 + 1) * PKS + rb + rr] * a2.y
                    + actT[(c0 + 2) * PKS + rb + rr] * a2.z
                    + actT[(c0 + 3) * PKS + rb + rr] * a2.w;
#pragma unroll
            for (int o = 16; o > 0; o >>= 1) p += __shfl_xor_sync(0xffffffffu, p, o);
            if (tc == 0 && row < NN) g_sdst[row] = p;
        }
    }

    ull acc[2][4];

    // ================= GEMM1: t1 = relu(h @ W1 + b1) =================
    {
#pragma unroll
        for (int p = 0; p < 2; p++)
#pragma unroll
            for (int c = 0; c < 4; c++) acc[p][c] = 0ull;
        const float4* Wg = reinterpret_cast<const float4*>(W1);
        float4* wb4 = reinterpret_cast<float4*>(wb);
#pragma unroll
        for (int j = 0; j < 4; j++) wb4[j * 256 + t] = Wg[j * 256 + t];
        __syncthreads();
        for (int ch = 0; ch < 4; ch++) {
            float4 pf0, pf1, pf2, pf3;
            if (ch < 3) {
                const float4* src = Wg + (ch + 1) * 1024;
                pf0 = src[t]; pf1 = src[256 + t]; pf2 = src[512 + t]; pf3 = src[768 + t];
            }
            const float* wc = wb + (ch & 1) * 4096;
            int kg0 = ch * 32;
#pragma unroll
            for (int kk = 0; kk < 32; kk++) {
                float4 b = *reinterpret_cast<const float4*>(&wc[kk * FF + c0]);
                ull a01, a23;
                lds2x2(a01, a23, &actT[(kg0 + kk) * PKS + rb]);
                ull b0 = pk(b.x, b.x), b1_ = pk(b.y, b.y), b2_ = pk(b.z, b.z), b3 = pk(b.w, b.w);
                fma2(acc[0][0], a01, b0); fma2(acc[0][1], a01, b1_);
                fma2(acc[0][2], a01, b2_); fma2(acc[0][3], a01, b3);
                fma2(acc[1][0], a23, b0); fma2(acc[1][1], a23, b1_);
                fma2(acc[1][2], a23, b2_); fma2(acc[1][3], a23, b3);
            }
            __syncthreads();
            if (ch < 3) {
                float4* dst = reinterpret_cast<float4*>(wb + ((ch + 1) & 1) * 4096);
                dst[t] = pf0; dst[256 + t] = pf1; dst[512 + t] = pf2; dst[768 + t] = pf3;
            }
            __syncthreads();
        }
        // epilogue: relu + bias -> overwrite actT with t1 (transposed)
        float4 bb = *reinterpret_cast<const float4*>(&b1[c0]);
        float bv[4] = {bb.x, bb.y, bb.z, bb.w};
#pragma unroll
        for (int p = 0; p < 2; p++)
#pragma unroll
            for (int c = 0; c < 4; c++) {
                float2 v = upk(acc[p][c]);
                v.x = fmaxf(v.x + bv[c], 0.f);
                v.y = fmaxf(v.y + bv[c], 0.f);
                *reinterpret_cast<ull*>(&actT[(c0 + c) * PKS + rb + 2 * p]) = pk(v.x, v.y);
            }
    }
    __syncthreads();

    // ================= GEMM2: M = t1 @ W2 + b2 =================
    {
#pragma unroll
        for (int p = 0; p < 2; p++)
#pragma unroll
            for (int c = 0; c < 4; c++) acc[p][c] = 0ull;
        const float4* Wg = reinterpret_cast<const float4*>(W2);
        float4* wb4 = reinterpret_cast<float4*>(wb);
#pragma unroll
        for (int j = 0; j < 4; j++) wb4[j * 256 + t] = Wg[j * 256 + t];
        __syncthreads();
        for (int ch = 0; ch < 4; ch++) {
            float4 pf0, pf1, pf2, pf3;
            if (ch < 3) {
                const float4* src = Wg + (ch + 1) * 1024;
                pf0 = src[t]; pf1 = src[256 + t]; pf2 = src[512 + t]; pf3 = src[768 + t];
            }
            const float* wc = wb + (ch & 1) * 4096;
            int kg0 = ch * 32;
#pragma unroll
            for (int kk = 0; kk < 32; kk++) {
                float4 b = *reinterpret_cast<const float4*>(&wc[kk * FF + c0]);
                ull a01, a23;
                lds2x2(a01, a23, &actT[(kg0 + kk) * PKS + rb]);
                ull b0 = pk(b.x, b.x), b1_ = pk(b.y, b.y), b2_ = pk(b.z, b.z), b3 = pk(b.w, b.w);
                fma2(acc[0][0], a01, b0); fma2(acc[0][1], a01, b1_);
                fma2(acc[0][2], a01, b2_); fma2(acc[0][3], a01, b3);
                fma2(acc[1][0], a23, b0); fma2(acc[1][1], a23, b1_);
                fma2(acc[1][2], a23, b2_); fma2(acc[1][3], a23, b3);
            }
            __syncthreads();
            if (ch < 3) {
                float4* dst = reinterpret_cast<float4*>(wb + ((ch + 1) & 1) * 4096);
                dst[t] = pf0; dst[256 + t] = pf1; dst[512 + t] = pf2; dst[768 + t] = pf3;
            }
            __syncthreads();
        }
    }

    // epilogue: bias, fp16 store, ssrc dot
    {
        float4 bb = *reinterpret_cast<const float4*>(&b2[c0]);
        float4 vv = *reinterpret_cast<const float4*>(&g_v[c0]);
        uint2* Mh2 = reinterpret_cast<uint2*>(g_Mh);
#pragma unroll
        for (int p = 0; p < 2; p++) {
            int rlo = row0 + rb + 2 * p;
            int rhi = rlo + 1;
            float2 m0 = upk(acc[p][0]), m1 = upk(acc[p][1]), m2 = upk(acc[p][2]), m3 = upk(acc[p][3]);
            float4 lo = {m0.x + bb.x, m1.x + bb.y, m2.x + bb.z, m3.x + bb.w};
            float4 hi = {m0.y + bb.x, m1.y + bb.y, m2.y + bb.z, m3.y + bb.w};
            if (rlo < NN) {
                __half2 h0 = __floats2half2_rn(lo.x, lo.y);
                __half2 h1 = __floats2half2_rn(lo.z, lo.w);
                Mh2[rlo * 32 + tc] = make_uint2(*reinterpret_cast<unsigned*>(&h0),
                                                *reinterpret_cast<unsigned*>(&h1));
            }
            if (rhi < NN) {
                __half2 h0 = __floats2half2_rn(hi.x, hi.y);
                __half2 h1 = __floats2half2_rn(hi.z, hi.w);
                Mh2[rhi * 32 + tc] = make_uint2(*reinterpret_cast<unsigned*>(&h0),
                                                *reinterpret_cast<unsigned*>(&h1));
            }
            float plo = lo.x * vv.x + lo.y * vv.y + lo.z * vv.z + lo.w * vv.w;
            float phi = hi.x * vv.x + hi.y * vv.y + hi.z * vv.z + hi.w * vv.w;
#pragma unroll
            for (int o = 16; o > 0; o >>= 1) {
                plo += __shfl_xor_sync(0xffffffffu, plo, o);
                phi += __shfl_xor_sync(0xffffffffu, phi, o);
            }
            if (tc == 0) {
                if (rlo < NN) g_ssrc[rlo] = plo;
                if (rhi < NN) g_ssrc[rhi] = phi;
            }
        }
    }
}

// ---------------- edge aggregation: one warp per dst ----------------
__global__ void k_edge() {
    int w = (blockIdx.x * blockDim.x + threadIdx.x) >> 5;
    int lane = threadIdx.x & 31;
    if (w >= NN) return;
    int beg = g_off[w];
    int ne = g_off[w + 1] - beg;
    float4* aggp = reinterpret_cast<float4*>(&g_agg[w * FF]) + lane;
    if (ne == 0) {
        float4 z = {0.f, 0.f, 0.f, 0.f};
        *aggp = z;
        return;
    }
    float mx = -1e30f;
    for (int j = lane; j < ne; j += 32) {
        int2 p = g_edge[beg + j];
        mx = fmaxf(mx, __int_as_float(p.y));
    }
#pragma unroll
    for (int o = 16; o > 0; o >>= 1) mx = fmaxf(mx, __shfl_xor_sync(0xffffffffu, mx, o));

    float4 acc = {0.f, 0.f, 0.f, 0.f};
    float den = 0.f;
    const uint2* Mh2 = reinterpret_cast<const uint2*>(g_Mh);
    int j = 0;
    for (; j + 4 <= ne; j += 4) {
        int2 e0 = g_edge[beg + j],     e1 = g_edge[beg + j + 1];
        int2 e2 = g_edge[beg + j + 2], e3 = g_edge[beg + j + 3];
        float ex0 = __expf(__int_as_float(e0.y) - mx);
        float ex1 = __expf(__int_as_float(e1.y) - mx);
        float ex2 = __expf(__int_as_float(e2.y) - mx);
        float ex3 = __expf(__int_as_float(e3.y) - mx);
        uint2 u0 = Mh2[e0.x * 32 + lane], u1 = Mh2[e1.x * 32 + lane];
        uint2 u2 = Mh2[e2.x * 32 + lane], u3 = Mh2[e3.x * 32 + lane];
        den += (ex0 + ex1) + (ex2 + ex3);
        float2 a0 = __half22float2(*reinterpret_cast<__half2*>(&u0.x));
        float2 b0 = __half22float2(*reinterpret_cast<__half2*>(&u0.y));
        float2 a1 = __half22float2(*reinterpret_cast<__half2*>(&u1.x));
        float2 b1 = __half22float2(*reinterpret_cast<__half2*>(&u1.y));
        float2 a2 = __half22float2(*reinterpret_cast<__half2*>(&u2.x));
        float2 b2 = __half22float2(*reinterpret_cast<__half2*>(&u2.y));
        float2 a3 = __half22float2(*reinterpret_cast<__half2*>(&u3.x));
        float2 b3 = __half22float2(*reinterpret_cast<__half2*>(&u3.y));
        acc.x += ex0 * a0.x + ex1 * a1.x + ex2 * a2.x + ex3 * a3.x;
        acc.y += ex0 * a0.y + ex1 * a1.y + ex2 * a2.y + ex3 * a3.y;
        acc.z += ex0 * b0.x + ex1 * b1.x + ex2 * b2.x + ex3 * b3.x;
        acc.w += ex0 * b0.y + ex1 * b1.y + ex2 * b2.y + ex3 * b3.y;
    }
    for (; j < ne; j++) {
        int2 e0 = g_edge[beg + j];
        float ex = __expf(__int_as_float(e0.y) - mx);
        uint2 u0 = Mh2[e0.x * 32 + lane];
        float2 a0 = __half22float2(*reinterpret_cast<__half2*>(&u0.x));
        float2 b0 = __half22float2(*reinterpret_cast<__half2*>(&u0.y));
        den += ex;
        acc.x += ex * a0.x; acc.y += ex * a0.y;
        acc.z += ex * b0.x; acc.w += ex * b0.y;
    }
    float inv = 1.f / (den + 1e-9f);
    acc.x *= inv; acc.y *= inv; acc.z *= inv; acc.w *= inv;
    *aggp = acc;
}

// ---------------- update + readout, smem-staged weights ----------------
__global__ void __launch_bounds__(256)
k_upd(const float* __restrict__ h,   const float* __restrict__ Wu,
      const float* __restrict__ bu,  const float* __restrict__ Wr1,
      const float* __restrict__ br1, const float* __restrict__ Wr2,
      const float* __restrict__ br2, float* __restrict__ out) {
    extern __shared__ float sm[];
    float* xsT = sm;                  // [256 k][36 r]; first 128 rows reused as hnT
    float* wb  = sm + 2 * FF * PKS;   // [2][32*128] (also holds full Wr1)
    int t = threadIdx.x;
    int tc = t & 31, tw = t >> 5;
    int c0 = 4 * tc, rb = 4 * tw;
    int row0 = blockIdx.x * TRW;

    for (int i = t; i < TRW * 256; i += 256) {
        int c = i & 255, r = i >> 8;
        int gr = row0 + r;
        float v = 0.f;
        if (gr < NN) v = (c < FF) ? g_agg[gr * FF + c] : h[gr * FF + (c - FF)];
        xsT[c * PKS + r] = v;
    }
    __syncthreads();

    ull acc[2][4];
#pragma unroll
    for (int p = 0; p < 2; p++)
#pragma unroll
        for (int c = 0; c < 4; c++) acc[p][c] = 0ull;

    // ======= GEMM-u: hn = relu([agg|h] @ Wu + bu), 8 chunks of 32 k =======
    {
        const float4* Wg = reinterpret_cast<const float4*>(Wu);
        float4* wb4 = reinterpret_cast<float4*>(wb);
#pragma unroll
        for (int j = 0; j < 4; j++) wb4[j * 256 + t] = Wg[j * 256 + t];
        __syncthreads();
        for (int ch = 0; ch < 8; ch++) {
            float4 pf0, pf1, pf2, pf3;
            if (ch < 7) {
                const float4* src = Wg + (ch + 1) * 1024;
                pf0 = src[t]; pf1 = src[256 + t]; pf2 = src[512 + t]; pf3 = src[768 + t];
            }
            const float* wc = wb + (ch & 1) * 4096;
            int kg0 = ch * 32;
#pragma unroll
            for (int kk = 0; kk < 32; kk++) {
                float4 b = *reinterpret_cast<const float4*>(&wc[kk * FF + c0]);
                ull a01, a23;
                lds2x2(a01, a23, &xsT[(kg0 + kk) * PKS + rb]);
                ull b0 = pk(b.x, b.x), b1_ = pk(b.y, b.y), b2_ = pk(b.z, b.z), b3 = pk(b.w, b.w);
                fma2(acc[0][0], a01, b0); fma2(acc[0][1], a01, b1_);
                fma2(acc[0][2], a01, b2_); fma2(acc[0][3], a01, b3);
                fma2(acc[1][0], a23, b0); fma2(acc[1][1], a23, b1_);
                fma2(acc[1][2], a23, b2_); fma2(acc[1][3], a23, b3);
            }
            __syncthreads();
            if (ch < 7) {
                float4* dst = reinterpret_cast<float4*>(wb + ((ch + 1) & 1) * 4096);
                dst[t] = pf0; dst[256 + t] = pf1; dst[512 + t] = pf2; dst[768 + t] = pf3;
            }
            __syncthreads();
        }
        // epilogue -> hnT (reuse xsT front region)
        float4 bb = *reinterpret_cast<const float4*>(&bu[c0]);
        float bv[4] = {bb.x, bb.y, bb.z, bb.w};
#pragma unroll
        for (int p = 0; p < 2; p++)
#pragma unroll
            for (int c = 0; c < 4; c++) {
                float2 v = upk(acc[p][c]);
                v.x = fmaxf(v.x + bv[c], 0.f);
                v.y = fmaxf(v.y + bv[c], 0.f);
                *reinterpret_cast<ull*>(&xsT[(c0 + c) * PKS + rb + 2 * p]) = pk(v.x, v.y);
            }
    }
    // stage full Wr1 (128x64 = 8192 floats) into wb
    {
        const float4* Wg = reinterpret_cast<const float4*>(Wr1);
        float4* wb4 = reinterpret_cast<float4*>(wb);
        __syncthreads();
#pragma unroll
        for (int j = 0; j < 8; j++) wb4[j * 256 + t] = Wg[j * 256 + t];
        __syncthreads();
    }

    // ======= readout: r1 = relu(hn @ Wr1 + br1); out = r1 @ Wr2 + br2 =======
    int c1 = 2 * tc;
    ull ar[2][2];
    ar[0][0] = ar[0][1] = ar[1][0] = ar[1][1] = 0ull;
#pragma unroll 8
    for (int k = 0; k < FF; k++) {
        float2 bw = *reinterpret_cast<const float2*>(&wb[k * HID + c1]);
        ull a01, a23;
        lds2x2(a01, a23, &xsT[k * PKS + rb]);
        ull bx = pk(bw.x, bw.x), by = pk(bw.y, bw.y);
        fma2(ar[0][0], a01, bx); fma2(ar[0][1], a01, by);
        fma2(ar[1][0], a23, bx); fma2(ar[1][1], a23, by);
    }
    {
        float2 w2  = *reinterpret_cast<const float2*>(&Wr2[c1]);
        float2 bb1 = *reinterpret_cast<const float2*>(&br1[c1]);
        float br2v = br2[0];
#pragma unroll
        for (int p = 0; p < 2; p++) {
            int rlo = row0 + rb + 2 * p;
            int rhi = rlo + 1;
            float2 q0 = upk(ar[p][0]);
            float2 q1 = upk(ar[p][1]);
            float plo = fmaxf(q0.x + bb1.x, 0.f) * w2.x + fmaxf(q1.x + bb1.y, 0.f) * w2.y;
            float phi = fmaxf(q0.y + bb1.x, 0.f) * w2.x + fmaxf(q1.y + bb1.y, 0.f) * w2.y;
#pragma unroll
            for (int o = 16; o > 0; o >>= 1) {
                plo += __shfl_xor_sync(0xffffffffu, plo, o);
                phi += __shfl_xor_sync(0xffffffffu, phi, o);
            }
            if (tc == 0) {
                if (rlo < NN) out[rlo] = plo + br2v;
                if (rhi < NN) out[rhi] = phi + br2v;
            }
        }
    }
}

// ---------------- launch ----------------
extern "C" void kernel_launch(void* const* d_in, const int* in_sizes, int n_in,
                              void* d_out, int out_size) {
    const float* h    = (const float*)d_in[0];
    const int*   src  = (const int*)d_in[1];
    const int*   dst  = (const int*)d_in[2];
    const float* W1   = (const float*)d_in[3];
    const float* b1   = (const float*)d_in[4];
    const float* W2   = (const float*)d_in[5];
    const float* b2   = (const float*)d_in[6];
    const float* nk   = (const float*)d_in[7];
    const float* attn = (const float*)d_in[8];
    const float* Wu   = (const float*)d_in[9];
    const float* bu   = (const float*)d_in[10];
    const float* Wr1  = (const float*)d_in[11];
    const float* br1  = (const float*)d_in[12];
    const float* Wr2  = (const float*)d_in[13];
    const float* br2  = (const float*)d_in[14];
    float* out = (float*)d_out;

    const int smem_node = (FF * PKS + 2 * 4096) * sizeof(float);      // 51200
    const int smem_upd  = (2 * FF * PKS + 2 * 4096) * sizeof(float);  // 69632
    cudaFuncSetAttribute(k_node, cudaFuncAttributeMaxDynamicSharedMemorySize, smem_node);
    cudaFuncSetAttribute(k_upd,  cudaFuncAttributeMaxDynamicSharedMemorySize, smem_upd);

    k_prep<<<41, 256>>>(nk, attn);
    k_hist<<<(EE / 4 + 255) / 256, 256>>>((const int4*)dst);
    k_scan<<<1, 1024>>>();
    k_node<<<(NN + TRW - 1) / TRW, 256, smem_node>>>(h, W1, b1, W2, b2, attn);
    k_scatter<<<(EE / 4 + 255) / 256, 256>>>((const int4*)src, (const int4*)dst);
    k_edge<<<(NN * 32 + 255) / 256, 256>>>();
    k_upd<<<(NN + TRW - 1) / TRW, 256, smem_upd>>>(h, Wu, bu, Wr1, br1, Wr2, br2, out);
}